// round 1
// baseline (speedup 1.0000x reference)
#include <cuda_runtime.h>
#include <math.h>

#define NN   8192
#define EE   262144
#define IND  512
#define HD1  256
#define HD2  128

// ---------------- scratch (device globals; no allocations allowed) ----------
__device__ int   g_deg_out[NN];
__device__ int   g_deg_in[NN];
__device__ float g_norm_src[NN];
__device__ float g_norm_dst[NN];
__device__ float g_y1[(size_t)NN * HD1];   // (x*norm_src)@W1
__device__ float g_a1[(size_t)NN * HD1];   // agg1 -> x1 (in place)
__device__ float g_y2[(size_t)NN * HD2];   // (x1*norm_src)@W2
__device__ float g_a2[(size_t)NN * HD2];   // agg2

// ---------------- small utility kernels -------------------------------------
__global__ void k_zero(float* __restrict__ p, int n) {
    int i = blockIdx.x * blockDim.x + threadIdx.x;
    if (i < n) p[i] = 0.f;
}

__global__ void k_zero_deg() {
    int i = blockIdx.x * blockDim.x + threadIdx.x;
    if (i < NN) { g_deg_out[i] = 0; g_deg_in[i] = 0; }
}

__global__ void k_degrees(const int* __restrict__ src, const int* __restrict__ dst) {
    int e = blockIdx.x * blockDim.x + threadIdx.x;
    if (e < EE) {
        atomicAdd(&g_deg_out[src[e]], 1);
        atomicAdd(&g_deg_in[dst[e]], 1);
    }
}

__global__ void k_norms() {
    int i = blockIdx.x * blockDim.x + threadIdx.x;
    if (i < NN) {
        g_norm_src[i] = rsqrtf(fmaxf((float)g_deg_out[i], 1.f));
        g_norm_dst[i] = rsqrtf(fmaxf((float)g_deg_in[i], 1.f));
    }
}

// ---------------- tiled SGEMM: C[M,Nc] = (diag(scale) * A[M,K]) @ B[K,Nc] ----
template<int BM, int BN, int BK, int TM, int TN>
__global__ void sgemm_nn_scaled(const float* __restrict__ A,
                                const float* __restrict__ rowScale,
                                const float* __restrict__ B,
                                float* __restrict__ C,
                                int M, int K, int Nc) {
    __shared__ float As[BK][BM + 1];
    __shared__ float Bs[BK][BN + 1];
    constexpr int THREADS = (BM / TM) * (BN / TN);
    const int tid = threadIdx.x;
    const int tx = tid % (BN / TN);
    const int ty = tid / (BN / TN);
    const int rowBase = blockIdx.y * BM;
    const int colBase = blockIdx.x * BN;

    float acc[TM][TN];
#pragma unroll
    for (int i = 0; i < TM; i++)
#pragma unroll
        for (int j = 0; j < TN; j++) acc[i][j] = 0.f;

    for (int k0 = 0; k0 < K; k0 += BK) {
#pragma unroll
        for (int i = tid; i < BM * BK; i += THREADS) {
            int m = i / BK, kk = i % BK;
            As[kk][m] = A[(size_t)(rowBase + m) * K + k0 + kk] * rowScale[rowBase + m];
        }
#pragma unroll
        for (int i = tid; i < BK * BN; i += THREADS) {
            int kk = i / BN, n = i % BN;
            Bs[kk][n] = B[(size_t)(k0 + kk) * Nc + colBase + n];
        }
        __syncthreads();
#pragma unroll
        for (int kk = 0; kk < BK; kk++) {
            float a[TM], b[TN];
#pragma unroll
            for (int i = 0; i < TM; i++) a[i] = As[kk][ty * TM + i];
#pragma unroll
            for (int j = 0; j < TN; j++) b[j] = Bs[kk][tx * TN + j];
#pragma unroll
            for (int i = 0; i < TM; i++)
#pragma unroll
                for (int j = 0; j < TN; j++) acc[i][j] = fmaf(a[i], b[j], acc[i][j]);
        }
        __syncthreads();
    }
#pragma unroll
    for (int i = 0; i < TM; i++) {
        int r = rowBase + ty * TM + i;
#pragma unroll
        for (int j = 0; j < TN; j++)
            C[(size_t)r * Nc + colBase + tx * TN + j] = acc[i][j];
    }
}

// ---------------- SpMM: agg[dst] += H[src], one warp per edge ----------------
template<int D>
__global__ void k_spmm(const float* __restrict__ H,
                       const int* __restrict__ src,
                       const int* __restrict__ dst,
                       float* __restrict__ agg) {
    int warp = (blockIdx.x * blockDim.x + threadIdx.x) >> 5;
    int lane = threadIdx.x & 31;
    if (warp >= EE) return;
    int s = __ldg(&src[warp]);
    int d = __ldg(&dst[warp]);
    const float* hs = H + (size_t)s * D;
    float* ad = agg + (size_t)d * D;
#pragma unroll
    for (int i = lane; i < D; i += 32) atomicAdd(ad + i, __ldg(hs + i));
}

// ---------------- epilogue: out = act(agg * norm_dst + b) -------------------
template<bool RELU, int D>
__global__ void k_epilogue(const float* __restrict__ agg,
                           const float* __restrict__ bias,
                           float* __restrict__ out) {
    int i = blockIdx.x * blockDim.x + threadIdx.x;
    if (i >= NN * D) return;
    int node = i / D;
    int d = i % D;
    float v = fmaf(agg[i], g_norm_dst[node], bias[d]);
    out[i] = RELU ? fmaxf(v, 0.f) : v;
}

// ---------------- logits = sigmoid(E @ E^T), K=128, 128x128 tiles -----------
__global__ void gemm_nt_sigmoid(const float* __restrict__ Emb,
                                float* __restrict__ L) {
    constexpr int BM = 128, BN = 128, BK = 32, TM = 8, TN = 8;
    __shared__ float As[BK][BM + 4];
    __shared__ float Bs[BK][BN + 4];
    const int tid = threadIdx.x;
    const int tx = tid % (BN / TN);   // 0..15
    const int ty = tid / (BN / TN);   // 0..15
    const int rowBase = blockIdx.y * BM;
    const int colBase = blockIdx.x * BN;

    float acc[TM][TN];
#pragma unroll
    for (int i = 0; i < TM; i++)
#pragma unroll
        for (int j = 0; j < TN; j++) acc[i][j] = 0.f;

    for (int k0 = 0; k0 < HD2; k0 += BK) {
#pragma unroll
        for (int i = tid; i < BM * BK; i += 256) {
            int m = i / BK, kk = i % BK;
            As[kk][m] = Emb[(size_t)(rowBase + m) * HD2 + k0 + kk];
        }
#pragma unroll
        for (int i = tid; i < BN * BK; i += 256) {
            int n = i / BK, kk = i % BK;
            Bs[kk][n] = Emb[(size_t)(colBase + n) * HD2 + k0 + kk];
        }
        __syncthreads();
#pragma unroll
        for (int kk = 0; kk < BK; kk++) {
            float4 a0 = *(const float4*)&As[kk][ty * TM];
            float4 a1 = *(const float4*)&As[kk][ty * TM + 4];
            float4 b0 = *(const float4*)&Bs[kk][tx * TN];
            float4 b1 = *(const float4*)&Bs[kk][tx * TN + 4];
            float a[TM] = {a0.x, a0.y, a0.z, a0.w, a1.x, a1.y, a1.z, a1.w};
            float b[TN] = {b0.x, b0.y, b0.z, b0.w, b1.x, b1.y, b1.z, b1.w};
#pragma unroll
            for (int i = 0; i < TM; i++)
#pragma unroll
                for (int j = 0; j < TN; j++) acc[i][j] = fmaf(a[i], b[j], acc[i][j]);
        }
        __syncthreads();
    }

#pragma unroll
    for (int i = 0; i < TM; i++) {
        size_t r = (size_t)(rowBase + ty * TM + i);
        float v[TN];
#pragma unroll
        for (int j = 0; j < TN; j++)
            v[j] = __fdividef(1.f, 1.f + __expf(-acc[i][j]));
        float4* p = (float4*)&L[r * NN + colBase + tx * TN];
        p[0] = make_float4(v[0], v[1], v[2], v[3]);
        p[1] = make_float4(v[4], v[5], v[6], v[7]);
    }
}

// ---------------- launch ------------------------------------------------------
extern "C" void kernel_launch(void* const* d_in, const int* in_sizes, int n_in,
                              void* d_out, int out_size) {
    const float* feat = (const float*)d_in[0];
    const int*   src  = (const int*)d_in[1];
    const int*   dst  = (const int*)d_in[2];
    const float* W1   = (const float*)d_in[3];
    const float* b1   = (const float*)d_in[4];
    const float* W2   = (const float*)d_in[5];
    const float* b2   = (const float*)d_in[6];

    float* out    = (float*)d_out;
    float* emb    = out;                       // [NN, HD2]
    float* logits = out + (size_t)NN * HD2;    // [NN, NN]

    float *y1, *a1, *y2, *a2, *nsrc;
    cudaGetSymbolAddress((void**)&y1, g_y1);
    cudaGetSymbolAddress((void**)&a1, g_a1);
    cudaGetSymbolAddress((void**)&y2, g_y2);
    cudaGetSymbolAddress((void**)&a2, g_a2);
    cudaGetSymbolAddress((void**)&nsrc, g_norm_src);

    // degrees + norms
    k_zero_deg<<<NN / 256, 256>>>();
    k_degrees<<<EE / 256, 256>>>(src, dst);
    k_norms<<<NN / 256, 256>>>();

    // layer 1: y1 = (x*norm_src)@W1 ; agg1 = scatter ; x1 = relu(agg1*norm_dst+b1)
    {
        dim3 grid(HD1 / 64, NN / 64);
        sgemm_nn_scaled<64, 64, 32, 4, 4><<<grid, 256>>>(feat, nsrc, W1, y1, NN, IND, HD1);
    }
    k_zero<<<(NN * HD1) / 256, 256>>>(a1, NN * HD1);
    k_spmm<HD1><<<(EE * 32) / 256, 256>>>(y1, src, dst, a1);
    k_epilogue<true, HD1><<<(NN * HD1) / 256, 256>>>(a1, b1, a1);

    // layer 2
    {
        dim3 grid(HD2 / 64, NN / 64);
        sgemm_nn_scaled<64, 64, 32, 4, 4><<<grid, 256>>>(a1, nsrc, W2, y2, NN, HD1, HD2);
    }
    k_zero<<<(NN * HD2) / 256, 256>>>(a2, NN * HD2);
    k_spmm<HD2><<<(EE * 32) / 256, 256>>>(y2, src, dst, a2);
    k_epilogue<false, HD2><<<(NN * HD2) / 256, 256>>>(a2, b2, emb);

    // dense reconstruction: logits = sigmoid(emb @ emb^T)
    {
        dim3 grid(NN / 128, NN / 128);
        gemm_nt_sigmoid<<<grid, 256>>>(emb, logits);
    }
}

// round 2
// speedup vs baseline: 1.7453x; 1.7453x over previous
#include <cuda_runtime.h>
#include <cuda_bf16.h>
#include <math.h>

#define NN   8192
#define EE   262144
#define IND  512
#define HD1  256
#define HD2  128

// ---------------- scratch (device globals; no allocations allowed) ----------
__device__ int   g_deg_out[NN];
__device__ int   g_deg_in[NN];
__device__ float g_norm_src[NN];
__device__ float g_norm_dst[NN];
__device__ float g_y1[(size_t)NN * HD1];
__device__ float g_a1[(size_t)NN * HD1];
__device__ float g_y2[(size_t)NN * HD2];
__device__ float g_a2[(size_t)NN * HD2];
__device__ __nv_bfloat16 g_ehi[(size_t)NN * HD2];
__device__ __nv_bfloat16 g_elo[(size_t)NN * HD2];

// ---------------- small utility kernels -------------------------------------
__global__ void k_zero(float* __restrict__ p, int n) {
    int i = blockIdx.x * blockDim.x + threadIdx.x;
    if (i < n) p[i] = 0.f;
}

__global__ void k_zero_deg() {
    int i = blockIdx.x * blockDim.x + threadIdx.x;
    if (i < NN) { g_deg_out[i] = 0; g_deg_in[i] = 0; }
}

__global__ void k_degrees(const int* __restrict__ src, const int* __restrict__ dst) {
    int e = blockIdx.x * blockDim.x + threadIdx.x;
    if (e < EE) {
        atomicAdd(&g_deg_out[src[e]], 1);
        atomicAdd(&g_deg_in[dst[e]], 1);
    }
}

__global__ void k_norms() {
    int i = blockIdx.x * blockDim.x + threadIdx.x;
    if (i < NN) {
        g_norm_src[i] = rsqrtf(fmaxf((float)g_deg_out[i], 1.f));
        g_norm_dst[i] = rsqrtf(fmaxf((float)g_deg_in[i], 1.f));
    }
}

// split emb into bf16 hi/lo
__global__ void k_split(const float* __restrict__ e,
                        __nv_bfloat16* __restrict__ hi,
                        __nv_bfloat16* __restrict__ lo) {
    int i = blockIdx.x * blockDim.x + threadIdx.x;
    if (i < NN * HD2) {
        float x = e[i];
        __nv_bfloat16 h = __float2bfloat16(x);
        hi[i] = h;
        lo[i] = __float2bfloat16(x - __bfloat162float(h));
    }
}

// ---------------- tiled SGEMM: C[M,Nc] = (diag(scale) * A[M,K]) @ B[K,Nc] ----
template<int BM, int BN, int BK, int TM, int TN>
__global__ void sgemm_nn_scaled(const float* __restrict__ A,
                                const float* __restrict__ rowScale,
                                const float* __restrict__ B,
                                float* __restrict__ C,
                                int M, int K, int Nc) {
    __shared__ float As[BK][BM + 1];
    __shared__ float Bs[BK][BN + 1];
    constexpr int THREADS = (BM / TM) * (BN / TN);
    const int tid = threadIdx.x;
    const int tx = tid % (BN / TN);
    const int ty = tid / (BN / TN);
    const int rowBase = blockIdx.y * BM;
    const int colBase = blockIdx.x * BN;

    float acc[TM][TN];
#pragma unroll
    for (int i = 0; i < TM; i++)
#pragma unroll
        for (int j = 0; j < TN; j++) acc[i][j] = 0.f;

    for (int k0 = 0; k0 < K; k0 += BK) {
#pragma unroll
        for (int i = tid; i < BM * BK; i += THREADS) {
            int m = i / BK, kk = i % BK;
            As[kk][m] = A[(size_t)(rowBase + m) * K + k0 + kk] * rowScale[rowBase + m];
        }
#pragma unroll
        for (int i = tid; i < BK * BN; i += THREADS) {
            int kk = i / BN, n = i % BN;
            Bs[kk][n] = B[(size_t)(k0 + kk) * Nc + colBase + n];
        }
        __syncthreads();
#pragma unroll
        for (int kk = 0; kk < BK; kk++) {
            float a[TM], b[TN];
#pragma unroll
            for (int i = 0; i < TM; i++) a[i] = As[kk][ty * TM + i];
#pragma unroll
            for (int j = 0; j < TN; j++) b[j] = Bs[kk][tx * TN + j];
#pragma unroll
            for (int i = 0; i < TM; i++)
#pragma unroll
                for (int j = 0; j < TN; j++) acc[i][j] = fmaf(a[i], b[j], acc[i][j]);
        }
        __syncthreads();
    }
#pragma unroll
    for (int i = 0; i < TM; i++) {
        int r = rowBase + ty * TM + i;
#pragma unroll
        for (int j = 0; j < TN; j++)
            C[(size_t)r * Nc + colBase + tx * TN + j] = acc[i][j];
    }
}

// ---------------- SpMM: agg[dst] += H[src], one warp per edge ----------------
template<int D>
__global__ void k_spmm(const float* __restrict__ H,
                       const int* __restrict__ src,
                       const int* __restrict__ dst,
                       float* __restrict__ agg) {
    int warp = (blockIdx.x * blockDim.x + threadIdx.x) >> 5;
    int lane = threadIdx.x & 31;
    if (warp >= EE) return;
    int s = __ldg(&src[warp]);
    int d = __ldg(&dst[warp]);
    const float* hs = H + (size_t)s * D;
    float* ad = agg + (size_t)d * D;
#pragma unroll
    for (int i = lane; i < D; i += 32) atomicAdd(ad + i, __ldg(hs + i));
}

// ---------------- epilogue: out = act(agg * norm_dst + b) -------------------
template<bool RELU, int D>
__global__ void k_epilogue(const float* __restrict__ agg,
                           const float* __restrict__ bias,
                           float* __restrict__ out) {
    int i = blockIdx.x * blockDim.x + threadIdx.x;
    if (i >= NN * D) return;
    int node = i / D;
    int d = i % D;
    float v = fmaf(agg[i], g_norm_dst[node], bias[d]);
    out[i] = RELU ? fmaxf(v, 0.f) : v;
}

// ================ reconstruction: logits = sigmoid(emb @ emb^T) ==============
// Symmetric: only upper-triangle 128x128 blocks computed, mirrored via smem.
// Precision: emb = hi + lo (bf16); z = hi.hi + hi.lo + lo.hi  (mma.sync bf16)
__device__ __forceinline__ void mma16816(float* c, const unsigned* a, const unsigned* b) {
    asm volatile(
        "mma.sync.aligned.m16n8k16.row.col.f32.bf16.bf16.f32 "
        "{%0,%1,%2,%3}, {%4,%5,%6,%7}, {%8,%9}, {%0,%1,%2,%3};"
        : "+f"(c[0]), "+f"(c[1]), "+f"(c[2]), "+f"(c[3])
        : "r"(a[0]), "r"(a[1]), "r"(a[2]), "r"(a[3]), "r"(b[0]), "r"(b[1]));
}

__device__ __forceinline__ float sigm(float x) {
    return __fdividef(1.f, 1.f + __expf(-x));
}

#define LDT 40   // smem leading dim (halfwords) for 32-col bf16 tiles

__global__ __launch_bounds__(256) void gemm_sym_sigmoid(float* __restrict__ L) {
    const int bi = blockIdx.y, bj = blockIdx.x;
    if (bj < bi) return;

    __shared__ __nv_bfloat16 As[128 * LDT];
    __shared__ __nv_bfloat16 Bs[128 * LDT];
    __shared__ float tbuf[32 * 132];

    const int tid = threadIdx.x;
    const int warp = tid >> 5, lane = tid & 31;
    const int wm = warp & 1, wn = warp >> 1;      // 2 x 4 warp grid, 64x32 per warp
    const int g = lane >> 2, t4 = lane & 3;

    const int rowBase = bi * 128, colBase = bj * 128;

    float c[4][4][4];
#pragma unroll
    for (int mi = 0; mi < 4; mi++)
#pragma unroll
        for (int nj = 0; nj < 4; nj++)
#pragma unroll
            for (int q = 0; q < 4; q++) c[mi][nj][q] = 0.f;

    const __nv_bfloat16* hiP = g_ehi;
    const __nv_bfloat16* loP = g_elo;
    const __nv_bfloat16* Aterm[3] = {hiP, hiP, loP};
    const __nv_bfloat16* Bterm[3] = {hiP, loP, hiP};

#pragma unroll 1
    for (int t = 0; t < 3; t++) {
        const __nv_bfloat16* Ag = Aterm[t] + (size_t)rowBase * HD2;
        const __nv_bfloat16* Bg = Bterm[t] + (size_t)colBase * HD2;
#pragma unroll 1
        for (int k0 = 0; k0 < HD2; k0 += 32) {
            // load 128x32 bf16 tiles (uint2 = 4 bf16 per op)
#pragma unroll
            for (int i = tid; i < 128 * 8; i += 256) {
                int r = i >> 3, cc = i & 7;
                *(uint2*)&As[r * LDT + cc * 4] =
                    *(const uint2*)&Ag[(size_t)r * HD2 + k0 + cc * 4];
                *(uint2*)&Bs[r * LDT + cc * 4] =
                    *(const uint2*)&Bg[(size_t)r * HD2 + k0 + cc * 4];
            }
            __syncthreads();
#pragma unroll
            for (int ks = 0; ks < 2; ks++) {
                const int kk = ks * 16;
                unsigned a[4][4], b[4][2];
#pragma unroll
                for (int mi = 0; mi < 4; mi++) {
                    const __nv_bfloat16* p = &As[(wm * 64 + mi * 16 + g) * LDT + kk + 2 * t4];
                    a[mi][0] = *(const unsigned*)p;
                    a[mi][1] = *(const unsigned*)(p + 8 * LDT);
                    a[mi][2] = *(const unsigned*)(p + 8);
                    a[mi][3] = *(const unsigned*)(p + 8 * LDT + 8);
                }
#pragma unroll
                for (int nj = 0; nj < 4; nj++) {
                    const __nv_bfloat16* p = &Bs[(wn * 32 + nj * 8 + g) * LDT + kk + 2 * t4];
                    b[nj][0] = *(const unsigned*)p;
                    b[nj][1] = *(const unsigned*)(p + 8);
                }
#pragma unroll
                for (int mi = 0; mi < 4; mi++)
#pragma unroll
                    for (int nj = 0; nj < 4; nj++)
                        mma16816(c[mi][nj], a[mi], b[nj]);
            }
            __syncthreads();
        }
    }

    // sigmoid in place
#pragma unroll
    for (int mi = 0; mi < 4; mi++)
#pragma unroll
        for (int nj = 0; nj < 4; nj++)
#pragma unroll
            for (int q = 0; q < 4; q++) c[mi][nj][q] = sigm(c[mi][nj][q]);

    // normal-orientation write
#pragma unroll
    for (int mi = 0; mi < 4; mi++) {
        int r = rowBase + wm * 64 + mi * 16 + g;
#pragma unroll
        for (int nj = 0; nj < 4; nj++) {
            int ccol = colBase + wn * 32 + nj * 8 + 2 * t4;
            float2 v0 = make_float2(c[mi][nj][0], c[mi][nj][1]);
            float2 v1 = make_float2(c[mi][nj][2], c[mi][nj][3]);
            *(float2*)&L[(size_t)r * NN + ccol] = v0;
            *(float2*)&L[(size_t)(r + 8) * NN + ccol] = v1;
        }
    }

    // mirrored write for off-diagonal blocks: L[colBase.., rowBase..] = acc^T
    if (bi != bj) {
#pragma unroll 1
        for (int ci = 0; ci < 4; ci++) {   // 32-column chunks, owned by warps with wn==ci
            __syncthreads();
            if (wn == ci) {
#pragma unroll
                for (int mi = 0; mi < 4; mi++) {
                    int rr = wm * 64 + mi * 16 + g;
#pragma unroll
                    for (int nj = 0; nj < 4; nj++) {
                        int cc = nj * 8 + 2 * t4;
                        tbuf[cc * 132 + rr]           = c[mi][nj][0];
                        tbuf[(cc + 1) * 132 + rr]     = c[mi][nj][1];
                        tbuf[cc * 132 + rr + 8]       = c[mi][nj][2];
                        tbuf[(cc + 1) * 132 + rr + 8] = c[mi][nj][3];
                    }
                }
            }
            __syncthreads();
#pragma unroll
            for (int i = tid; i < 32 * 32; i += 256) {
                int rr2 = i >> 5, c4 = i & 31;
                float4 v = *(float4*)&tbuf[rr2 * 132 + c4 * 4];
                *(float4*)&L[(size_t)(colBase + ci * 32 + rr2) * NN + rowBase + c4 * 4] = v;
            }
        }
    }
}

// ---------------- launch ------------------------------------------------------
extern "C" void kernel_launch(void* const* d_in, const int* in_sizes, int n_in,
                              void* d_out, int out_size) {
    const float* feat = (const float*)d_in[0];
    const int*   src  = (const int*)d_in[1];
    const int*   dst  = (const int*)d_in[2];
    const float* W1   = (const float*)d_in[3];
    const float* b1   = (const float*)d_in[4];
    const float* W2   = (const float*)d_in[5];
    const float* b2   = (const float*)d_in[6];

    float* out    = (float*)d_out;
    float* emb    = out;                       // [NN, HD2]
    float* logits = out + (size_t)NN * HD2;    // [NN, NN]

    float *y1, *a1, *y2, *a2, *nsrc;
    __nv_bfloat16 *ehi, *elo;
    cudaGetSymbolAddress((void**)&y1, g_y1);
    cudaGetSymbolAddress((void**)&a1, g_a1);
    cudaGetSymbolAddress((void**)&y2, g_y2);
    cudaGetSymbolAddress((void**)&a2, g_a2);
    cudaGetSymbolAddress((void**)&nsrc, g_norm_src);
    cudaGetSymbolAddress((void**)&ehi, g_ehi);
    cudaGetSymbolAddress((void**)&elo, g_elo);

    // degrees + norms
    k_zero_deg<<<NN / 256, 256>>>();
    k_degrees<<<EE / 256, 256>>>(src, dst);
    k_norms<<<NN / 256, 256>>>();

    // layer 1
    {
        dim3 grid(HD1 / 64, NN / 128);
        sgemm_nn_scaled<128, 64, 32, 8, 4><<<grid, 256>>>(feat, nsrc, W1, y1, NN, IND, HD1);
    }
    k_zero<<<(NN * HD1) / 256, 256>>>(a1, NN * HD1);
    k_spmm<HD1><<<(EE * 32) / 256, 256>>>(y1, src, dst, a1);
    k_epilogue<true, HD1><<<(NN * HD1) / 256, 256>>>(a1, b1, a1);

    // layer 2
    {
        dim3 grid(HD2 / 64, NN / 128);
        sgemm_nn_scaled<128, 64, 32, 8, 4><<<grid, 256>>>(a1, nsrc, W2, y2, NN, HD1, HD2);
    }
    k_zero<<<(NN * HD2) / 256, 256>>>(a2, NN * HD2);
    k_spmm<HD2><<<(EE * 32) / 256, 256>>>(y2, src, dst, a2);
    k_epilogue<false, HD2><<<(NN * HD2) / 256, 256>>>(a2, b2, emb);

    // split emb into bf16 hi/lo
    k_split<<<(NN * HD2) / 256, 256>>>(emb, ehi, elo);

    // logits = sigmoid(emb @ emb^T), symmetric tensor-core GEMM
    {
        dim3 grid(NN / 128, NN / 128);
        gemm_sym_sigmoid<<<grid, 256>>>(logits);
    }
}

// round 3
// speedup vs baseline: 1.8598x; 1.0656x over previous
#include <cuda_runtime.h>
#include <cuda_bf16.h>
#include <math.h>

#define NN   8192
#define EE   262144
#define IND  512
#define HD1  256
#define HD2  128

// ---------------- scratch (device globals; no allocations allowed) ----------
__device__ int   g_deg_out[NN];
__device__ int   g_deg_in[NN];
__device__ float g_norm_src[NN];
__device__ float g_norm_dst[NN];
__device__ int   g_csr_off[NN + 1];
__device__ int   g_csr_pos[NN];
__device__ int   g_csr_src[EE];

__device__ __nv_bfloat16 g_fhi[(size_t)NN * IND];
__device__ __nv_bfloat16 g_flo[(size_t)NN * IND];
__device__ __nv_bfloat16 g_w1thi[(size_t)HD1 * IND];
__device__ __nv_bfloat16 g_w1tlo[(size_t)HD1 * IND];
__device__ __nv_bfloat16 g_w2thi[(size_t)HD2 * HD1];
__device__ __nv_bfloat16 g_w2tlo[(size_t)HD2 * HD1];
__device__ float g_y1[(size_t)NN * HD1];
__device__ float g_y2[(size_t)NN * HD2];
__device__ __nv_bfloat16 g_x1hi[(size_t)NN * HD1];
__device__ __nv_bfloat16 g_x1lo[(size_t)NN * HD1];
__device__ __nv_bfloat16 g_ehi[(size_t)NN * HD2];
__device__ __nv_bfloat16 g_elo[(size_t)NN * HD2];

// ---------------- graph preprocessing ---------------------------------------
__global__ void k_zero_deg() {
    int i = blockIdx.x * blockDim.x + threadIdx.x;
    if (i < NN) { g_deg_out[i] = 0; g_deg_in[i] = 0; }
}

__global__ void k_degrees(const int* __restrict__ src, const int* __restrict__ dst) {
    int e = blockIdx.x * blockDim.x + threadIdx.x;
    if (e < EE) {
        atomicAdd(&g_deg_out[src[e]], 1);
        atomicAdd(&g_deg_in[dst[e]], 1);
    }
}

__global__ void k_norms() {
    int i = blockIdx.x * blockDim.x + threadIdx.x;
    if (i < NN) {
        g_norm_src[i] = rsqrtf(fmaxf((float)g_deg_out[i], 1.f));
        g_norm_dst[i] = rsqrtf(fmaxf((float)g_deg_in[i], 1.f));
    }
}

// exclusive scan of in-degrees (single block, 1024 threads, 8 items each)
__global__ void k_scan_csr() {
    __shared__ int part[1024];
    const int tid = threadIdx.x;
    const int base = tid * 8;
    int local[8];
    int s = 0;
#pragma unroll
    for (int j = 0; j < 8; j++) { local[j] = s; s += g_deg_in[base + j]; }
    part[tid] = s;
    __syncthreads();
    for (int off = 1; off < 1024; off <<= 1) {
        int v = (tid >= off) ? part[tid - off] : 0;
        __syncthreads();
        part[tid] += v;
        __syncthreads();
    }
    int pre = tid ? part[tid - 1] : 0;
#pragma unroll
    for (int j = 0; j < 8; j++) {
        int o = pre + local[j];
        g_csr_off[base + j] = o;
        g_csr_pos[base + j] = o;
    }
    if (tid == 1023) g_csr_off[NN] = part[1023];
}

__global__ void k_csr_fill(const int* __restrict__ src, const int* __restrict__ dst) {
    int e = blockIdx.x * blockDim.x + threadIdx.x;
    if (e < EE) {
        int d = dst[e];
        int p = atomicAdd(&g_csr_pos[d], 1);
        g_csr_src[p] = src[e];
    }
}

// ---------------- prep: feature & weight bf16 splits ------------------------
__global__ void k_prep_feat(const float* __restrict__ feat) {
    int i = blockIdx.x * blockDim.x + threadIdx.x;
    if (i < NN * IND) {
        int node = i >> 9;   // IND = 512
        float x = feat[i] * g_norm_src[node];
        __nv_bfloat16 h = __float2bfloat16(x);
        g_fhi[i] = h;
        g_flo[i] = __float2bfloat16(x - __bfloat162float(h));
    }
}

// W [K][N] row-major -> Wt hi/lo [N][K]
__global__ void k_prep_w(const float* __restrict__ W, int K, int Nc,
                         __nv_bfloat16* __restrict__ tHi,
                         __nv_bfloat16* __restrict__ tLo) {
    int i = blockIdx.x * blockDim.x + threadIdx.x;
    if (i < K * Nc) {
        int k = i / Nc, n = i % Nc;
        float x = W[i];
        __nv_bfloat16 h = __float2bfloat16(x);
        tHi[(size_t)n * K + k] = h;
        tLo[(size_t)n * K + k] = __float2bfloat16(x - __bfloat162float(h));
    }
}

// ---------------- bf16 split-precision MMA building blocks ------------------
__device__ __forceinline__ void mma16816(float* c, const unsigned* a, const unsigned* b) {
    asm volatile(
        "mma.sync.aligned.m16n8k16.row.col.f32.bf16.bf16.f32 "
        "{%0,%1,%2,%3}, {%4,%5,%6,%7}, {%8,%9}, {%0,%1,%2,%3};"
        : "+f"(c[0]), "+f"(c[1]), "+f"(c[2]), "+f"(c[3])
        : "r"(a[0]), "r"(a[1]), "r"(a[2]), "r"(a[3]), "r"(b[0]), "r"(b[1]));
}

__device__ __forceinline__ float sigm(float x) {
    return __fdividef(1.f, 1.f + __expf(-x));
}

#define LDT 40   // smem leading dim (halfwords) for 32-col bf16 tiles

// ---------------- layer GEMM: C[M,Nc] = (Ahi+Alo) @ (Whi+Wlo)^T --------------
// A: [M,K] bf16 hi/lo rows.  Bt: [Nc,K] bf16 hi/lo rows (pre-transposed W).
// 3-term: hi.hi + hi.lo + lo.hi.  128x128 block, 8 warps (2x4), 64x32/warp.
__global__ __launch_bounds__(256) void gemm_tc(
    const __nv_bfloat16* __restrict__ Ahi, const __nv_bfloat16* __restrict__ Alo,
    const __nv_bfloat16* __restrict__ Bhi, const __nv_bfloat16* __restrict__ Blo,
    float* __restrict__ C, int K, int Nc) {
    __shared__ __nv_bfloat16 As[128 * LDT];
    __shared__ __nv_bfloat16 Bs[128 * LDT];

    const int tid = threadIdx.x;
    const int warp = tid >> 5, lane = tid & 31;
    const int wm = warp & 1, wn = warp >> 1;
    const int g = lane >> 2, t4 = lane & 3;
    const int rowBase = blockIdx.y * 128, colBase = blockIdx.x * 128;

    float c[4][4][4];
#pragma unroll
    for (int mi = 0; mi < 4; mi++)
#pragma unroll
        for (int nj = 0; nj < 4; nj++)
#pragma unroll
            for (int q = 0; q < 4; q++) c[mi][nj][q] = 0.f;

    const __nv_bfloat16* Aterm[3] = {Ahi, Ahi, Alo};
    const __nv_bfloat16* Bterm[3] = {Bhi, Blo, Bhi};

#pragma unroll 1
    for (int t = 0; t < 3; t++) {
        const __nv_bfloat16* Ag = Aterm[t] + (size_t)rowBase * K;
        const __nv_bfloat16* Bg = Bterm[t] + (size_t)colBase * K;
#pragma unroll 1
        for (int k0 = 0; k0 < K; k0 += 32) {
#pragma unroll
            for (int i = tid; i < 128 * 8; i += 256) {
                int r = i >> 3, cc = i & 7;
                *(uint2*)&As[r * LDT + cc * 4] =
                    *(const uint2*)&Ag[(size_t)r * K + k0 + cc * 4];
                *(uint2*)&Bs[r * LDT + cc * 4] =
                    *(const uint2*)&Bg[(size_t)r * K + k0 + cc * 4];
            }
            __syncthreads();
#pragma unroll
            for (int ks = 0; ks < 2; ks++) {
                const int kk = ks * 16;
                unsigned a[4][4], b[4][2];
#pragma unroll
                for (int mi = 0; mi < 4; mi++) {
                    const __nv_bfloat16* p = &As[(wm * 64 + mi * 16 + g) * LDT + kk + 2 * t4];
                    a[mi][0] = *(const unsigned*)p;
                    a[mi][1] = *(const unsigned*)(p + 8 * LDT);
                    a[mi][2] = *(const unsigned*)(p + 8);
                    a[mi][3] = *(const unsigned*)(p + 8 * LDT + 8);
                }
#pragma unroll
                for (int nj = 0; nj < 4; nj++) {
                    const __nv_bfloat16* p = &Bs[(wn * 32 + nj * 8 + g) * LDT + kk + 2 * t4];
                    b[nj][0] = *(const unsigned*)p;
                    b[nj][1] = *(const unsigned*)(p + 8);
                }
#pragma unroll
                for (int mi = 0; mi < 4; mi++)
#pragma unroll
                    for (int nj = 0; nj < 4; nj++)
                        mma16816(c[mi][nj], a[mi], b[nj]);
            }
            __syncthreads();
        }
    }

#pragma unroll
    for (int mi = 0; mi < 4; mi++) {
        int r = rowBase + wm * 64 + mi * 16 + g;
#pragma unroll
        for (int nj = 0; nj < 4; nj++) {
            int ccol = colBase + wn * 32 + nj * 8 + 2 * t4;
            *(float2*)&C[(size_t)r * Nc + ccol] = make_float2(c[mi][nj][0], c[mi][nj][1]);
            *(float2*)&C[(size_t)(r + 8) * Nc + ccol] = make_float2(c[mi][nj][2], c[mi][nj][3]);
        }
    }
}

// ---------------- SpMM gather: one warp per destination node ----------------
// out = act(sum_{in-edges} Y[src] * norm_dst + bias); optionally *norm_src,
// emitted as bf16 hi/lo (next GEMM input) and optionally fp32.
template<int D, bool RELU, bool NSRC, bool WF32>
__global__ void k_spmm_gather(const float* __restrict__ Y,
                              const float* __restrict__ bias,
                              float* __restrict__ outF,
                              __nv_bfloat16* __restrict__ outHi,
                              __nv_bfloat16* __restrict__ outLo) {
    constexpr int VEC = D / 32;
    int node = (blockIdx.x * blockDim.x + threadIdx.x) >> 5;
    int lane = threadIdx.x & 31;
    if (node >= NN) return;
    const int beg = g_csr_off[node], end = g_csr_off[node + 1];

    float acc[VEC];
#pragma unroll
    for (int j = 0; j < VEC; j++) acc[j] = 0.f;

#pragma unroll 2
    for (int e = beg; e < end; e++) {
        int s = __ldg(&g_csr_src[e]);
        const float4* p = (const float4*)(Y + (size_t)s * D + lane * VEC);
#pragma unroll
        for (int q = 0; q < VEC / 4; q++) {
            float4 u = __ldg(p + q);
            acc[q * 4 + 0] += u.x;
            acc[q * 4 + 1] += u.y;
            acc[q * 4 + 2] += u.z;
            acc[q * 4 + 3] += u.w;
        }
    }

    const float nd = g_norm_dst[node];
    const float ns = NSRC ? g_norm_src[node] : 1.f;
    const size_t base = (size_t)node * D + lane * VEC;
#pragma unroll
    for (int j = 0; j < VEC; j++) {
        float v = fmaf(acc[j], nd, __ldg(&bias[lane * VEC + j]));
        if (RELU) v = fmaxf(v, 0.f);
        if (WF32) outF[base + j] = v;
        float w = v * ns;
        __nv_bfloat16 h = __float2bfloat16(w);
        outHi[base + j] = h;
        outLo[base + j] = __float2bfloat16(w - __bfloat162float(h));
    }
}

// ================ reconstruction: logits = sigmoid(emb @ emb^T) ==============
__global__ __launch_bounds__(256) void gemm_sym_sigmoid(float* __restrict__ L) {
    const int bi = blockIdx.y, bj = blockIdx.x;
    if (bj < bi) return;

    __shared__ __nv_bfloat16 As[128 * LDT];
    __shared__ __nv_bfloat16 Bs[128 * LDT];
    __shared__ float tbuf[32 * 132];

    const int tid = threadIdx.x;
    const int warp = tid >> 5, lane = tid & 31;
    const int wm = warp & 1, wn = warp >> 1;
    const int g = lane >> 2, t4 = lane & 3;
    const int rowBase = bi * 128, colBase = bj * 128;

    float c[4][4][4];
#pragma unroll
    for (int mi = 0; mi < 4; mi++)
#pragma unroll
        for (int nj = 0; nj < 4; nj++)
#pragma unroll
            for (int q = 0; q < 4; q++) c[mi][nj][q] = 0.f;

    const __nv_bfloat16* hiP = g_ehi;
    const __nv_bfloat16* loP = g_elo;
    const __nv_bfloat16* Aterm[3] = {hiP, hiP, loP};
    const __nv_bfloat16* Bterm[3] = {hiP, loP, hiP};

#pragma unroll 1
    for (int t = 0; t < 3; t++) {
        const __nv_bfloat16* Ag = Aterm[t] + (size_t)rowBase * HD2;
        const __nv_bfloat16* Bg = Bterm[t] + (size_t)colBase * HD2;
#pragma unroll 1
        for (int k0 = 0; k0 < HD2; k0 += 32) {
#pragma unroll
            for (int i = tid; i < 128 * 8; i += 256) {
                int r = i >> 3, cc = i & 7;
                *(uint2*)&As[r * LDT + cc * 4] =
                    *(const uint2*)&Ag[(size_t)r * HD2 + k0 + cc * 4];
                *(uint2*)&Bs[r * LDT + cc * 4] =
                    *(const uint2*)&Bg[(size_t)r * HD2 + k0 + cc * 4];
            }
            __syncthreads();
#pragma unroll
            for (int ks = 0; ks < 2; ks++) {
                const int kk = ks * 16;
                unsigned a[4][4], b[4][2];
#pragma unroll
                for (int mi = 0; mi < 4; mi++) {
                    const __nv_bfloat16* p = &As[(wm * 64 + mi * 16 + g) * LDT + kk + 2 * t4];
                    a[mi][0] = *(const unsigned*)p;
                    a[mi][1] = *(const unsigned*)(p + 8 * LDT);
                    a[mi][2] = *(const unsigned*)(p + 8);
                    a[mi][3] = *(const unsigned*)(p + 8 * LDT + 8);
                }
#pragma unroll
                for (int nj = 0; nj < 4; nj++) {
                    const __nv_bfloat16* p = &Bs[(wn * 32 + nj * 8 + g) * LDT + kk + 2 * t4];
                    b[nj][0] = *(const unsigned*)p;
                    b[nj][1] = *(const unsigned*)(p + 8);
                }
#pragma unroll
                for (int mi = 0; mi < 4; mi++)
#pragma unroll
                    for (int nj = 0; nj < 4; nj++)
                        mma16816(c[mi][nj], a[mi], b[nj]);
            }
            __syncthreads();
        }
    }

#pragma unroll
    for (int mi = 0; mi < 4; mi++)
#pragma unroll
        for (int nj = 0; nj < 4; nj++)
#pragma unroll
            for (int q = 0; q < 4; q++) c[mi][nj][q] = sigm(c[mi][nj][q]);

#pragma unroll
    for (int mi = 0; mi < 4; mi++) {
        int r = rowBase + wm * 64 + mi * 16 + g;
#pragma unroll
        for (int nj = 0; nj < 4; nj++) {
            int ccol = colBase + wn * 32 + nj * 8 + 2 * t4;
            *(float2*)&L[(size_t)r * NN + ccol] = make_float2(c[mi][nj][0], c[mi][nj][1]);
            *(float2*)&L[(size_t)(r + 8) * NN + ccol] = make_float2(c[mi][nj][2], c[mi][nj][3]);
        }
    }

    if (bi != bj) {
#pragma unroll 1
        for (int ci = 0; ci < 4; ci++) {
            __syncthreads();
            if (wn == ci) {
#pragma unroll
                for (int mi = 0; mi < 4; mi++) {
                    int rr = wm * 64 + mi * 16 + g;
#pragma unroll
                    for (int nj = 0; nj < 4; nj++) {
                        int cc = nj * 8 + 2 * t4;
                        tbuf[cc * 132 + rr]           = c[mi][nj][0];
                        tbuf[(cc + 1) * 132 + rr]     = c[mi][nj][1];
                        tbuf[cc * 132 + rr + 8]       = c[mi][nj][2];
                        tbuf[(cc + 1) * 132 + rr + 8] = c[mi][nj][3];
                    }
                }
            }
            __syncthreads();
#pragma unroll
            for (int i = tid; i < 32 * 32; i += 256) {
                int rr2 = i >> 5, c4 = i & 31;
                float4 v = *(float4*)&tbuf[rr2 * 132 + c4 * 4];
                *(float4*)&L[(size_t)(colBase + ci * 32 + rr2) * NN + rowBase + c4 * 4] = v;
            }
        }
    }
}

// ---------------- launch ------------------------------------------------------
extern "C" void kernel_launch(void* const* d_in, const int* in_sizes, int n_in,
                              void* d_out, int out_size) {
    const float* feat = (const float*)d_in[0];
    const int*   src  = (const int*)d_in[1];
    const int*   dst  = (const int*)d_in[2];
    const float* W1   = (const float*)d_in[3];
    const float* b1   = (const float*)d_in[4];
    const float* W2   = (const float*)d_in[5];
    const float* b2   = (const float*)d_in[6];

    float* out    = (float*)d_out;
    float* emb    = out;                       // [NN, HD2]
    float* logits = out + (size_t)NN * HD2;    // [NN, NN]

    float *y1, *y2;
    __nv_bfloat16 *fhi, *flo, *w1thi, *w1tlo, *w2thi, *w2tlo, *x1hi, *x1lo, *ehi, *elo;
    cudaGetSymbolAddress((void**)&y1, g_y1);
    cudaGetSymbolAddress((void**)&y2, g_y2);
    cudaGetSymbolAddress((void**)&fhi, g_fhi);
    cudaGetSymbolAddress((void**)&flo, g_flo);
    cudaGetSymbolAddress((void**)&w1thi, g_w1thi);
    cudaGetSymbolAddress((void**)&w1tlo, g_w1tlo);
    cudaGetSymbolAddress((void**)&w2thi, g_w2thi);
    cudaGetSymbolAddress((void**)&w2tlo, g_w2tlo);
    cudaGetSymbolAddress((void**)&x1hi, g_x1hi);
    cudaGetSymbolAddress((void**)&x1lo, g_x1lo);
    cudaGetSymbolAddress((void**)&ehi, g_ehi);
    cudaGetSymbolAddress((void**)&elo, g_elo);

    // graph preprocessing
    k_zero_deg<<<NN / 256, 256>>>();
    k_degrees<<<EE / 256, 256>>>(src, dst);
    k_norms<<<NN / 256, 256>>>();
    k_scan_csr<<<1, 1024>>>();
    k_csr_fill<<<EE / 256, 256>>>(src, dst);

    // input prep
    k_prep_feat<<<(NN * IND) / 256, 256>>>(feat);
    k_prep_w<<<(IND * HD1) / 256, 256>>>(W1, IND, HD1, w1thi, w1tlo);
    k_prep_w<<<(HD1 * HD2) / 256, 256>>>(W2, HD1, HD2, w2thi, w2tlo);

    // layer 1: y1 = (x*nsrc)@W1  -> gather -> x1 = relu(.)*nsrc (bf16 split)
    gemm_tc<<<dim3(HD1 / 128, NN / 128), 256>>>(fhi, flo, w1thi, w1tlo, y1, IND, HD1);
    k_spmm_gather<HD1, true, true, false><<<(NN * 32) / 256, 256>>>(
        y1, b1, nullptr, x1hi, x1lo);

    // layer 2: y2 = x1s@W2 -> gather -> emb (fp32) + bf16 split
    gemm_tc<<<dim3(HD2 / 128, NN / 128), 256>>>(x1hi, x1lo, w2thi, w2tlo, y2, HD1, HD2);
    k_spmm_gather<HD2, false, false, true><<<(NN * 32) / 256, 256>>>(
        y2, b2, emb, ehi, elo);

    // logits = sigmoid(emb @ emb^T), symmetric tensor-core GEMM
    gemm_sym_sigmoid<<<dim3(NN / 128, NN / 128), 256>>>(logits);
}

// round 4
// speedup vs baseline: 2.0174x; 1.0847x over previous
#include <cuda_runtime.h>
#include <cuda_bf16.h>
#include <math.h>

#define NN   8192
#define EE   262144
#define IND  512
#define HD1  256
#define HD2  128

// ---------------- scratch (device globals; no allocations allowed) ----------
__device__ int   g_deg_out[NN];
__device__ int   g_deg_in[NN];
__device__ float g_norm_src[NN];
__device__ float g_norm_dst[NN];
__device__ int   g_csr_off[NN + 1];
__device__ int   g_csr_pos[NN];
__device__ int   g_csr_src[EE];

__device__ __nv_bfloat16 g_fhi[(size_t)NN * IND];
__device__ __nv_bfloat16 g_flo[(size_t)NN * IND];
__device__ __nv_bfloat16 g_w1thi[(size_t)HD1 * IND];
__device__ __nv_bfloat16 g_w1tlo[(size_t)HD1 * IND];
__device__ __nv_bfloat16 g_w2thi[(size_t)HD2 * HD1];
__device__ __nv_bfloat16 g_w2tlo[(size_t)HD2 * HD1];
__device__ float g_y1[(size_t)NN * HD1];
__device__ float g_y2[(size_t)NN * HD2];
__device__ __nv_bfloat16 g_x1hi[(size_t)NN * HD1];
__device__ __nv_bfloat16 g_x1lo[(size_t)NN * HD1];
__device__ __nv_bfloat16 g_ehi[(size_t)NN * HD2];
__device__ __nv_bfloat16 g_elo[(size_t)NN * HD2];

// ---------------- graph preprocessing ---------------------------------------
__global__ void k_zero_deg() {
    int i = blockIdx.x * blockDim.x + threadIdx.x;
    if (i < NN) { g_deg_out[i] = 0; g_deg_in[i] = 0; }
}

__global__ void k_degrees(const int* __restrict__ src, const int* __restrict__ dst) {
    int e = blockIdx.x * blockDim.x + threadIdx.x;
    if (e < EE) {
        atomicAdd(&g_deg_out[src[e]], 1);
        atomicAdd(&g_deg_in[dst[e]], 1);
    }
}

__global__ void k_norms() {
    int i = blockIdx.x * blockDim.x + threadIdx.x;
    if (i < NN) {
        g_norm_src[i] = rsqrtf(fmaxf((float)g_deg_out[i], 1.f));
        g_norm_dst[i] = rsqrtf(fmaxf((float)g_deg_in[i], 1.f));
    }
}

// exclusive scan of in-degrees: 1024 threads, 8 items each, warp shuffles
__global__ void k_scan_csr() {
    __shared__ int wsum[32];
    const int tid = threadIdx.x, lane = tid & 31, wid = tid >> 5;
    const int base = tid * 8;
    int local[8];
    int s = 0;
#pragma unroll
    for (int j = 0; j < 8; j++) { local[j] = s; s += g_deg_in[base + j]; }
    int inc = s;
#pragma unroll
    for (int d = 1; d < 32; d <<= 1) {
        int v = __shfl_up_sync(0xffffffffu, inc, d);
        if (lane >= d) inc += v;
    }
    if (lane == 31) wsum[wid] = inc;
    __syncthreads();
    if (wid == 0) {
        int v = wsum[lane];
        int i2 = v;
#pragma unroll
        for (int d = 1; d < 32; d <<= 1) {
            int u = __shfl_up_sync(0xffffffffu, i2, d);
            if (lane >= d) i2 += u;
        }
        wsum[lane] = i2 - v;   // exclusive
    }
    __syncthreads();
    int off = wsum[wid] + inc - s;
#pragma unroll
    for (int j = 0; j < 8; j++) {
        int o = off + local[j];
        g_csr_off[base + j] = o;
        g_csr_pos[base + j] = o;
    }
    if (tid == 0) g_csr_off[NN] = EE;
}

__global__ void k_csr_fill(const int* __restrict__ src, const int* __restrict__ dst) {
    int e = blockIdx.x * blockDim.x + threadIdx.x;
    if (e < EE) {
        int d = dst[e];
        int p = atomicAdd(&g_csr_pos[d], 1);
        g_csr_src[p] = src[e];
    }
}

// ---------------- prep: feature & weight bf16 splits ------------------------
__global__ void k_prep_feat(const float* __restrict__ feat) {
    int i4 = blockIdx.x * blockDim.x + threadIdx.x;
    if (i4 < (NN * IND) / 4) {
        int i = i4 * 4;
        int node = i >> 9;   // IND = 512
        float ns = g_norm_src[node];
        float4 u = __ldg((const float4*)&feat[i]);
        float x[4] = {u.x * ns, u.y * ns, u.z * ns, u.w * ns};
        __nv_bfloat162 h01, h23, l01, l23;
        __nv_bfloat16 h;
#define SPLIT1(v, HH, LL) h = __float2bfloat16(v); HH = h; LL = __float2bfloat16((v) - __bfloat162float(h));
        SPLIT1(x[0], h01.x, l01.x); SPLIT1(x[1], h01.y, l01.y);
        SPLIT1(x[2], h23.x, l23.x); SPLIT1(x[3], h23.y, l23.y);
        *(uint2*)&g_fhi[i] = make_uint2(*(unsigned*)&h01, *(unsigned*)&h23);
        *(uint2*)&g_flo[i] = make_uint2(*(unsigned*)&l01, *(unsigned*)&l23);
    }
}

// W [K][N] row-major -> Wt hi/lo [N][K]
__global__ void k_prep_w(const float* __restrict__ W, int K, int Nc,
                         __nv_bfloat16* __restrict__ tHi,
                         __nv_bfloat16* __restrict__ tLo) {
    int i = blockIdx.x * blockDim.x + threadIdx.x;
    if (i < K * Nc) {
        int k = i / Nc, n = i % Nc;
        float x = W[i];
        __nv_bfloat16 h = __float2bfloat16(x);
        tHi[(size_t)n * K + k] = h;
        tLo[(size_t)n * K + k] = __float2bfloat16(x - __bfloat162float(h));
    }
}

// ---------------- bf16 split-precision MMA building blocks ------------------
__device__ __forceinline__ void mma16816(float* c, const unsigned* a, const unsigned* b) {
    asm volatile(
        "mma.sync.aligned.m16n8k16.row.col.f32.bf16.bf16.f32 "
        "{%0,%1,%2,%3}, {%4,%5,%6,%7}, {%8,%9}, {%0,%1,%2,%3};"
        : "+f"(c[0]), "+f"(c[1]), "+f"(c[2]), "+f"(c[3])
        : "r"(a[0]), "r"(a[1]), "r"(a[2]), "r"(a[3]), "r"(b[0]), "r"(b[1]));
}

__device__ __forceinline__ float sigm(float x) {
    return __fdividef(1.f, 1.f + __expf(-x));
}

#define LDT 40   // smem leading dim (halfwords) for 32-col bf16 tiles

// ---------------- layer GEMM: C[M,Nc] = (Ahi+Alo) @ (Whi+Wlo)^T --------------
// BM = MI*32 rows per block; 8 warps (2 x 4); warp tile (MI*16) x 32.
template<int MI>
__global__ __launch_bounds__(256) void gemm_tc(
    const __nv_bfloat16* __restrict__ Ahi, const __nv_bfloat16* __restrict__ Alo,
    const __nv_bfloat16* __restrict__ Bhi, const __nv_bfloat16* __restrict__ Blo,
    float* __restrict__ C, int K, int Nc) {
    constexpr int BM = MI * 32;
    __shared__ __nv_bfloat16 As[BM * LDT];
    __shared__ __nv_bfloat16 Bs[128 * LDT];

    const int tid = threadIdx.x;
    const int warp = tid >> 5, lane = tid & 31;
    const int wm = warp & 1, wn = warp >> 1;
    const int g = lane >> 2, t4 = lane & 3;
    const int rowBase = blockIdx.y * BM, colBase = blockIdx.x * 128;

    float c[MI][4][4];
#pragma unroll
    for (int mi = 0; mi < MI; mi++)
#pragma unroll
        for (int nj = 0; nj < 4; nj++)
#pragma unroll
            for (int q = 0; q < 4; q++) c[mi][nj][q] = 0.f;

    const __nv_bfloat16* Aterm[3] = {Ahi, Ahi, Alo};
    const __nv_bfloat16* Bterm[3] = {Bhi, Blo, Bhi};

#pragma unroll 1
    for (int t = 0; t < 3; t++) {
        const __nv_bfloat16* Ag = Aterm[t] + (size_t)rowBase * K;
        const __nv_bfloat16* Bg = Bterm[t] + (size_t)colBase * K;
#pragma unroll 1
        for (int k0 = 0; k0 < K; k0 += 32) {
#pragma unroll
            for (int i = tid; i < BM * 8; i += 256) {
                int r = i >> 3, cc = i & 7;
                *(uint2*)&As[r * LDT + cc * 4] =
                    *(const uint2*)&Ag[(size_t)r * K + k0 + cc * 4];
            }
#pragma unroll
            for (int i = tid; i < 128 * 8; i += 256) {
                int r = i >> 3, cc = i & 7;
                *(uint2*)&Bs[r * LDT + cc * 4] =
                    *(const uint2*)&Bg[(size_t)r * K + k0 + cc * 4];
            }
            __syncthreads();
#pragma unroll
            for (int ks = 0; ks < 2; ks++) {
                const int kk = ks * 16;
                unsigned a[MI][4], b[4][2];
#pragma unroll
                for (int mi = 0; mi < MI; mi++) {
                    const __nv_bfloat16* p = &As[(wm * (MI * 16) + mi * 16 + g) * LDT + kk + 2 * t4];
                    a[mi][0] = *(const unsigned*)p;
                    a[mi][1] = *(const unsigned*)(p + 8 * LDT);
                    a[mi][2] = *(const unsigned*)(p + 8);
                    a[mi][3] = *(const unsigned*)(p + 8 * LDT + 8);
                }
#pragma unroll
                for (int nj = 0; nj < 4; nj++) {
                    const __nv_bfloat16* p = &Bs[(wn * 32 + nj * 8 + g) * LDT + kk + 2 * t4];
                    b[nj][0] = *(const unsigned*)p;
                    b[nj][1] = *(const unsigned*)(p + 8);
                }
#pragma unroll
                for (int mi = 0; mi < MI; mi++)
#pragma unroll
                    for (int nj = 0; nj < 4; nj++)
                        mma16816(c[mi][nj], a[mi], b[nj]);
            }
            __syncthreads();
        }
    }

#pragma unroll
    for (int mi = 0; mi < MI; mi++) {
        int r = rowBase + wm * (MI * 16) + mi * 16 + g;
#pragma unroll
        for (int nj = 0; nj < 4; nj++) {
            int ccol = colBase + wn * 32 + nj * 8 + 2 * t4;
            *(float2*)&C[(size_t)r * Nc + ccol] = make_float2(c[mi][nj][0], c[mi][nj][1]);
            *(float2*)&C[(size_t)(r + 8) * Nc + ccol] = make_float2(c[mi][nj][2], c[mi][nj][3]);
        }
    }
}

// ---------------- SpMM gather: WPN warps per destination node ----------------
// out = act(sum_{in-edges} Y[src] * norm_dst + bias); optionally *norm_src,
// emitted as bf16 hi/lo and optionally fp32. 4 floats per lane, MLP=4 loop.
template<int D, int WPN, bool RELU, bool NSRC, bool WF32>
__global__ void k_spmm_gather(const float* __restrict__ Y,
                              const float* __restrict__ bias,
                              float* __restrict__ outF,
                              __nv_bfloat16* __restrict__ outHi,
                              __nv_bfloat16* __restrict__ outLo) {
    int gw = (blockIdx.x * blockDim.x + threadIdx.x) >> 5;
    int lane = threadIdx.x & 31;
    int node = gw / WPN, part = gw % WPN;
    if (node >= NN) return;
    const int off = part * (D / WPN) + lane * 4;
    const int beg = g_csr_off[node], end = g_csr_off[node + 1];
    const int* sp = g_csr_src;

    float4 a0 = {0,0,0,0}, a1 = {0,0,0,0}, a2 = {0,0,0,0}, a3 = {0,0,0,0};
    int e = beg;
#pragma unroll 1
    for (; e + 4 <= end; e += 4) {
        int s0 = __ldg(sp + e),     s1 = __ldg(sp + e + 1);
        int s2 = __ldg(sp + e + 2), s3 = __ldg(sp + e + 3);
        float4 u0 = __ldg((const float4*)(Y + (size_t)s0 * D + off));
        float4 u1 = __ldg((const float4*)(Y + (size_t)s1 * D + off));
        float4 u2 = __ldg((const float4*)(Y + (size_t)s2 * D + off));
        float4 u3 = __ldg((const float4*)(Y + (size_t)s3 * D + off));
        a0.x += u0.x; a0.y += u0.y; a0.z += u0.z; a0.w += u0.w;
        a1.x += u1.x; a1.y += u1.y; a1.z += u1.z; a1.w += u1.w;
        a2.x += u2.x; a2.y += u2.y; a2.z += u2.z; a2.w += u2.w;
        a3.x += u3.x; a3.y += u3.y; a3.z += u3.z; a3.w += u3.w;
    }
#pragma unroll 1
    for (; e < end; e++) {
        int s = __ldg(sp + e);
        float4 u = __ldg((const float4*)(Y + (size_t)s * D + off));
        a0.x += u.x; a0.y += u.y; a0.z += u.z; a0.w += u.w;
    }
    float v[4];
    v[0] = (a0.x + a1.x) + (a2.x + a3.x);
    v[1] = (a0.y + a1.y) + (a2.y + a3.y);
    v[2] = (a0.z + a1.z) + (a2.z + a3.z);
    v[3] = (a0.w + a1.w) + (a2.w + a3.w);

    const float nd = g_norm_dst[node];
    const float ns = NSRC ? g_norm_src[node] : 1.f;
    const size_t base = (size_t)node * D + off;

    __nv_bfloat162 h01, h23, l01, l23;
    float4 fout;
    float* fo = (float*)&fout;
#pragma unroll
    for (int j = 0; j < 4; j++) {
        float w = fmaf(v[j], nd, __ldg(&bias[off + j]));
        if (RELU) w = fmaxf(w, 0.f);
        fo[j] = w;
        w *= ns;
        __nv_bfloat16 h = __float2bfloat16(w);
        __nv_bfloat16 l = __float2bfloat16(w - __bfloat162float(h));
        if (j == 0) { h01.x = h; l01.x = l; }
        if (j == 1) { h01.y = h; l01.y = l; }
        if (j == 2) { h23.x = h; l23.x = l; }
        if (j == 3) { h23.y = h; l23.y = l; }
    }
    if (WF32) *(float4*)&outF[base] = fout;
    *(uint2*)&outHi[base] = make_uint2(*(unsigned*)&h01, *(unsigned*)&h23);
    *(uint2*)&outLo[base] = make_uint2(*(unsigned*)&l01, *(unsigned*)&l23);
}

// ================ reconstruction: logits = sigmoid(emb @ emb^T) ==============
// Triangular launch: 2080 CTAs, bi<=bj decode. Dynamic smem reused:
// As/Bs (20.5KB) during MMA, then full 128x128 transpose buffer (67.6KB).
__global__ __launch_bounds__(256) void gemm_sym_sigmoid(float* __restrict__ L) {
    extern __shared__ char dyn[];
    __nv_bfloat16* As = (__nv_bfloat16*)dyn;
    __nv_bfloat16* Bs = As + 128 * LDT;
    float* tb = (float*)dyn;

    const int t = blockIdx.x;
    int bi = (int)((129.0f - sqrtf(16641.0f - 8.0f * (float)t)) * 0.5f);
    while (bi * (129 - bi) / 2 > t) bi--;
    while ((bi + 1) * (128 - bi) / 2 <= t) bi++;
    const int bj = bi + (t - bi * (129 - bi) / 2);

    const int tid = threadIdx.x;
    const int warp = tid >> 5, lane = tid & 31;
    const int wm = warp & 1, wn = warp >> 1;
    const int g = lane >> 2, t4 = lane & 3;
    const int rowBase = bi * 128, colBase = bj * 128;

    float c[4][4][4];
#pragma unroll
    for (int mi = 0; mi < 4; mi++)
#pragma unroll
        for (int nj = 0; nj < 4; nj++)
#pragma unroll
            for (int q = 0; q < 4; q++) c[mi][nj][q] = 0.f;

    const __nv_bfloat16* hiP = g_ehi;
    const __nv_bfloat16* loP = g_elo;
    const __nv_bfloat16* Aterm[3] = {hiP, hiP, loP};
    const __nv_bfloat16* Bterm[3] = {hiP, loP, hiP};

#pragma unroll 1
    for (int t3 = 0; t3 < 3; t3++) {
        const __nv_bfloat16* Ag = Aterm[t3] + (size_t)rowBase * HD2;
        const __nv_bfloat16* Bg = Bterm[t3] + (size_t)colBase * HD2;
#pragma unroll 1
        for (int k0 = 0; k0 < HD2; k0 += 32) {
#pragma unroll
            for (int i = tid; i < 128 * 8; i += 256) {
                int r = i >> 3, cc = i & 7;
                *(uint2*)&As[r * LDT + cc * 4] =
                    *(const uint2*)&Ag[(size_t)r * HD2 + k0 + cc * 4];
                *(uint2*)&Bs[r * LDT + cc * 4] =
                    *(const uint2*)&Bg[(size_t)r * HD2 + k0 + cc * 4];
            }
            __syncthreads();
#pragma unroll
            for (int ks = 0; ks < 2; ks++) {
                const int kk = ks * 16;
                unsigned a[4][4], b[4][2];
#pragma unroll
                for (int mi = 0; mi < 4; mi++) {
                    const __nv_bfloat16* p = &As[(wm * 64 + mi * 16 + g) * LDT + kk + 2 * t4];
                    a[mi][0] = *(const unsigned*)p;
                    a[mi][1] = *(const unsigned*)(p + 8 * LDT);
                    a[mi][2] = *(const unsigned*)(p + 8);
                    a[mi][3] = *(const unsigned*)(p + 8 * LDT + 8);
                }
#pragma unroll
                for (int nj = 0; nj < 4; nj++) {
                    const __nv_bfloat16* p = &Bs[(wn * 32 + nj * 8 + g) * LDT + kk + 2 * t4];
                    b[nj][0] = *(const unsigned*)p;
                    b[nj][1] = *(const unsigned*)(p + 8);
                }
#pragma unroll
                for (int mi = 0; mi < 4; mi++)
#pragma unroll
                    for (int nj = 0; nj < 4; nj++)
                        mma16816(c[mi][nj], a[mi], b[nj]);
            }
            __syncthreads();
        }
    }

    // sigmoid
#pragma unroll
    for (int mi = 0; mi < 4; mi++)
#pragma unroll
        for (int nj = 0; nj < 4; nj++)
#pragma unroll
            for (int q = 0; q < 4; q++) c[mi][nj][q] = sigm(c[mi][nj][q]);

    // direct-orientation store from registers
#pragma unroll
    for (int mi = 0; mi < 4; mi++) {
        int r = rowBase + wm * 64 + mi * 16 + g;
#pragma unroll
        for (int nj = 0; nj < 4; nj++) {
            int ccol = colBase + wn * 32 + nj * 8 + 2 * t4;
            *(float2*)&L[(size_t)r * NN + ccol] = make_float2(c[mi][nj][0], c[mi][nj][1]);
            *(float2*)&L[(size_t)(r + 8) * NN + ccol] = make_float2(c[mi][nj][2], c[mi][nj][3]);
        }
    }

    // mirrored store via full 128x128 transpose in smem (reuses As/Bs region)
    if (bi != bj) {
        // last k0 iteration ended with __syncthreads(); As/Bs are dead.
#pragma unroll
        for (int mi = 0; mi < 4; mi++) {
            int rr = wm * 64 + mi * 16 + g;
#pragma unroll
            for (int nj = 0; nj < 4; nj++) {
                int cc = wn * 32 + nj * 8 + 2 * t4;
                tb[cc * 132 + rr]           = c[mi][nj][0];
                tb[(cc + 1) * 132 + rr]     = c[mi][nj][1];
                tb[cc * 132 + rr + 8]       = c[mi][nj][2];
                tb[(cc + 1) * 132 + rr + 8] = c[mi][nj][3];
            }
        }
        __syncthreads();
#pragma unroll 4
        for (int i = tid; i < 128 * 32; i += 256) {
            int r2 = i >> 5, c4 = i & 31;
            float4 v = *(float4*)&tb[r2 * 132 + c4 * 4];
            *(float4*)&L[(size_t)(colBase + r2) * NN + rowBase + c4 * 4] = v;
        }
    }
}

// ---------------- launch ------------------------------------------------------
extern "C" void kernel_launch(void* const* d_in, const int* in_sizes, int n_in,
                              void* d_out, int out_size) {
    const float* feat = (const float*)d_in[0];
    const int*   src  = (const int*)d_in[1];
    const int*   dst  = (const int*)d_in[2];
    const float* W1   = (const float*)d_in[3];
    const float* b1   = (const float*)d_in[4];
    const float* W2   = (const float*)d_in[5];
    const float* b2   = (const float*)d_in[6];

    float* out    = (float*)d_out;
    float* emb    = out;                       // [NN, HD2]
    float* logits = out + (size_t)NN * HD2;    // [NN, NN]

    float *y1, *y2;
    __nv_bfloat16 *fhi, *flo, *w1thi, *w1tlo, *w2thi, *w2tlo, *x1hi, *x1lo, *ehi, *elo;
    cudaGetSymbolAddress((void**)&y1, g_y1);
    cudaGetSymbolAddress((void**)&y2, g_y2);
    cudaGetSymbolAddress((void**)&fhi, g_fhi);
    cudaGetSymbolAddress((void**)&flo, g_flo);
    cudaGetSymbolAddress((void**)&w1thi, g_w1thi);
    cudaGetSymbolAddress((void**)&w1tlo, g_w1tlo);
    cudaGetSymbolAddress((void**)&w2thi, g_w2thi);
    cudaGetSymbolAddress((void**)&w2tlo, g_w2tlo);
    cudaGetSymbolAddress((void**)&x1hi, g_x1hi);
    cudaGetSymbolAddress((void**)&x1lo, g_x1lo);
    cudaGetSymbolAddress((void**)&ehi, g_ehi);
    cudaGetSymbolAddress((void**)&elo, g_elo);

    static bool attr_set = false;
    if (!attr_set) {
        cudaFuncSetAttribute(gemm_sym_sigmoid,
                             cudaFuncAttributeMaxDynamicSharedMemorySize, 128 * 132 * 4);
        attr_set = true;
    }

    // graph preprocessing
    k_zero_deg<<<NN / 256, 256>>>();
    k_degrees<<<EE / 256, 256>>>(src, dst);
    k_norms<<<NN / 256, 256>>>();
    k_scan_csr<<<1, 1024>>>();
    k_csr_fill<<<EE / 256, 256>>>(src, dst);

    // input prep
    k_prep_feat<<<(NN * IND / 4) / 256, 256>>>(feat);
    k_prep_w<<<(IND * HD1) / 256, 256>>>(W1, IND, HD1, w1thi, w1tlo);
    k_prep_w<<<(HD1 * HD2) / 256, 256>>>(W2, HD1, HD2, w2thi, w2tlo);

    // layer 1: y1 = (x*nsrc)@W1 -> gather -> x1 = relu(.)*nsrc (bf16 split)
    gemm_tc<4><<<dim3(HD1 / 128, NN / 128), 256>>>(fhi, flo, w1thi, w1tlo, y1, IND, HD1);
    k_spmm_gather<HD1, 2, true, true, false><<<(NN * 2 * 32) / 256, 256>>>(
        y1, b1, nullptr, x1hi, x1lo);

    // layer 2: y2 = x1s@W2 -> gather -> emb (fp32) + bf16 split
    gemm_tc<2><<<dim3(HD2 / 128, NN / 64), 256>>>(x1hi, x1lo, w2thi, w2tlo, y2, HD1, HD2);
    k_spmm_gather<HD2, 1, false, false, true><<<(NN * 32) / 256, 256>>>(
        y2, b2, emb, ehi, elo);

    // logits = sigmoid(emb @ emb^T), triangular symmetric tensor-core GEMM
    gemm_sym_sigmoid<<<2080, 256, 128 * 132 * 4>>>(logits);
}

// round 5
// speedup vs baseline: 3.6405x; 1.8045x over previous
#include <cuda_runtime.h>
#include <cuda_bf16.h>
#include <math.h>

#define NN   8192
#define EE   262144
#define IND  512
#define HD1  256
#define HD2  128

// ---------------- scratch (device globals; no allocations allowed) ----------
__device__ int   g_deg_out[NN];
__device__ int   g_deg_in[NN];
__device__ float g_norm_src[NN];
__device__ float g_norm_dst[NN];
__device__ int   g_csr_off[NN + 1];
__device__ int   g_csr_pos[NN];
__device__ int   g_csr_src[EE];

__device__ __nv_bfloat16 g_fhi[(size_t)NN * IND];
__device__ __nv_bfloat16 g_flo[(size_t)NN * IND];
__device__ __nv_bfloat16 g_w1thi[(size_t)HD1 * IND];
__device__ __nv_bfloat16 g_w1tlo[(size_t)HD1 * IND];
__device__ __nv_bfloat16 g_w2thi[(size_t)HD2 * HD1];
__device__ __nv_bfloat16 g_w2tlo[(size_t)HD2 * HD1];
__device__ float g_y1[(size_t)NN * HD1];
__device__ float g_y2[(size_t)NN * HD2];
__device__ __nv_bfloat16 g_x1hi[(size_t)NN * HD1];
__device__ __nv_bfloat16 g_x1lo[(size_t)NN * HD1];
__device__ __nv_bfloat16 g_ehi[(size_t)NN * HD2];
__device__ __nv_bfloat16 g_elo[(size_t)NN * HD2];

// ---------------- graph preprocessing ---------------------------------------
__global__ void k_zero_deg() {
    int i = blockIdx.x * blockDim.x + threadIdx.x;
    if (i < NN) { g_deg_out[i] = 0; g_deg_in[i] = 0; }
}

__global__ void k_degrees(const int* __restrict__ src, const int* __restrict__ dst) {
    int e = blockIdx.x * blockDim.x + threadIdx.x;
    if (e < EE) {
        atomicAdd(&g_deg_out[src[e]], 1);
        atomicAdd(&g_deg_in[dst[e]], 1);
    }
}

__global__ void k_norms() {
    int i = blockIdx.x * blockDim.x + threadIdx.x;
    if (i < NN) {
        g_norm_src[i] = rsqrtf(fmaxf((float)g_deg_out[i], 1.f));
        g_norm_dst[i] = rsqrtf(fmaxf((float)g_deg_in[i], 1.f));
    }
}

// exclusive scan of in-degrees: 1024 threads, 8 items each, int4-coalesced
__global__ void k_scan_csr() {
    __shared__ int wsum[32];
    const int tid = threadIdx.x, lane = tid & 31, wid = tid >> 5;
    int4 d0 = *(const int4*)&g_deg_in[tid * 8];
    int4 d1 = *(const int4*)&g_deg_in[tid * 8 + 4];
    int v[8] = {d0.x, d0.y, d0.z, d0.w, d1.x, d1.y, d1.z, d1.w};
    int local[8];
    int s = 0;
#pragma unroll
    for (int j = 0; j < 8; j++) { local[j] = s; s += v[j]; }
    int inc = s;
#pragma unroll
    for (int d = 1; d < 32; d <<= 1) {
        int u = __shfl_up_sync(0xffffffffu, inc, d);
        if (lane >= d) inc += u;
    }
    if (lane == 31) wsum[wid] = inc;
    __syncthreads();
    if (wid == 0) {
        int w = wsum[lane];
        int i2 = w;
#pragma unroll
        for (int d = 1; d < 32; d <<= 1) {
            int u = __shfl_up_sync(0xffffffffu, i2, d);
            if (lane >= d) i2 += u;
        }
        wsum[lane] = i2 - w;   // exclusive
    }
    __syncthreads();
    int off = wsum[wid] + inc - s;
    int4 o0 = make_int4(off + local[0], off + local[1], off + local[2], off + local[3]);
    int4 o1 = make_int4(off + local[4], off + local[5], off + local[6], off + local[7]);
    *(int4*)&g_csr_off[tid * 8] = o0;
    *(int4*)&g_csr_off[tid * 8 + 4] = o1;
    *(int4*)&g_csr_pos[tid * 8] = o0;
    *(int4*)&g_csr_pos[tid * 8 + 4] = o1;
    if (tid == 0) g_csr_off[NN] = EE;
}

__global__ void k_csr_fill(const int* __restrict__ src, const int* __restrict__ dst) {
    int e = blockIdx.x * blockDim.x + threadIdx.x;
    if (e < EE) {
        int d = dst[e];
        int p = atomicAdd(&g_csr_pos[d], 1);
        g_csr_src[p] = src[e];
    }
}

// ---------------- prep: feature & weight bf16 splits ------------------------
__global__ void k_prep_feat(const float* __restrict__ feat) {
    int i4 = blockIdx.x * blockDim.x + threadIdx.x;
    if (i4 < (NN * IND) / 4) {
        int i = i4 * 4;
        int node = i >> 9;   // IND = 512
        float ns = g_norm_src[node];
        float4 u = __ldg((const float4*)&feat[i]);
        float x[4] = {u.x * ns, u.y * ns, u.z * ns, u.w * ns};
        __nv_bfloat162 h01, h23, l01, l23;
        __nv_bfloat16 h;
#define SPLIT1(v, HH, LL) h = __float2bfloat16(v); HH = h; LL = __float2bfloat16((v) - __bfloat162float(h));
        SPLIT1(x[0], h01.x, l01.x); SPLIT1(x[1], h01.y, l01.y);
        SPLIT1(x[2], h23.x, l23.x); SPLIT1(x[3], h23.y, l23.y);
        *(uint2*)&g_fhi[i] = make_uint2(*(unsigned*)&h01, *(unsigned*)&h23);
        *(uint2*)&g_flo[i] = make_uint2(*(unsigned*)&l01, *(unsigned*)&l23);
    }
}

// fused: W1 [IND][HD1] -> w1t hi/lo [HD1][IND];  W2 [HD1][HD2] -> w2t hi/lo
__global__ void k_prep_w_both(const float* __restrict__ W1, const float* __restrict__ W2) {
    int i = blockIdx.x * blockDim.x + threadIdx.x;
    if (i < IND * HD1) {
        int k = i / HD1, n = i % HD1;
        float x = W1[i];
        __nv_bfloat16 h = __float2bfloat16(x);
        g_w1thi[(size_t)n * IND + k] = h;
        g_w1tlo[(size_t)n * IND + k] = __float2bfloat16(x - __bfloat162float(h));
    } else {
        int j = i - IND * HD1;
        if (j < HD1 * HD2) {
            int k = j / HD2, n = j % HD2;
            float x = W2[j];
            __nv_bfloat16 h = __float2bfloat16(x);
            g_w2thi[(size_t)n * HD1 + k] = h;
            g_w2tlo[(size_t)n * HD1 + k] = __float2bfloat16(x - __bfloat162float(h));
        }
    }
}

// ---------------- bf16 split-precision MMA building blocks ------------------
__device__ __forceinline__ void mma16816(float* c, const unsigned* a, const unsigned* b) {
    asm volatile(
        "mma.sync.aligned.m16n8k16.row.col.f32.bf16.bf16.f32 "
        "{%0,%1,%2,%3}, {%4,%5,%6,%7}, {%8,%9}, {%0,%1,%2,%3};"
        : "+f"(c[0]), "+f"(c[1]), "+f"(c[2]), "+f"(c[3])
        : "r"(a[0]), "r"(a[1]), "r"(a[2]), "r"(a[3]), "r"(b[0]), "r"(b[1]));
}

__device__ __forceinline__ float sigm(float x) {
    return __fdividef(1.f, 1.f + __expf(-x));
}

#define LDT 40   // smem leading dim (halfwords) for 32-col bf16 tiles

// ---------------- layer GEMM: C[M,Nc] = (Ahi+Alo) @ (Bhi+Blo)^T --------------
// Per k0 chunk: load hi+lo of A and B, run all 3 split terms. 8 warps (2x4).
template<int MI>
__global__ __launch_bounds__(256, 2) void gemm_tc(
    const __nv_bfloat16* __restrict__ Ahi, const __nv_bfloat16* __restrict__ Alo,
    const __nv_bfloat16* __restrict__ Bhi, const __nv_bfloat16* __restrict__ Blo,
    float* __restrict__ C, int K, int Nc) {
    constexpr int BM = MI * 32;
    __shared__ __nv_bfloat16 sAh[BM * LDT], sAl[BM * LDT];
    __shared__ __nv_bfloat16 sBh[128 * LDT], sBl[128 * LDT];

    const int tid = threadIdx.x;
    const int warp = tid >> 5, lane = tid & 31;
    const int wm = warp & 1, wn = warp >> 1;
    const int g = lane >> 2, t4 = lane & 3;
    const int rowBase = blockIdx.y * BM, colBase = blockIdx.x * 128;

    float c[MI][4][4];
#pragma unroll
    for (int mi = 0; mi < MI; mi++)
#pragma unroll
        for (int nj = 0; nj < 4; nj++)
#pragma unroll
            for (int q = 0; q < 4; q++) c[mi][nj][q] = 0.f;

#pragma unroll 1
    for (int k0 = 0; k0 < K; k0 += 32) {
#pragma unroll
        for (int i = tid; i < BM * 8; i += 256) {
            int r = i >> 3, cc = i & 7;
            size_t gidx = (size_t)(rowBase + r) * K + k0 + cc * 4;
            *(uint2*)&sAh[r * LDT + cc * 4] = *(const uint2*)&Ahi[gidx];
            *(uint2*)&sAl[r * LDT + cc * 4] = *(const uint2*)&Alo[gidx];
        }
#pragma unroll
        for (int i = tid; i < 128 * 8; i += 256) {
            int r = i >> 3, cc = i & 7;
            size_t gidx = (size_t)(colBase + r) * K + k0 + cc * 4;
            *(uint2*)&sBh[r * LDT + cc * 4] = *(const uint2*)&Bhi[gidx];
            *(uint2*)&sBl[r * LDT + cc * 4] = *(const uint2*)&Blo[gidx];
        }
        __syncthreads();
#pragma unroll
        for (int ks = 0; ks < 2; ks++) {
            const int kk = ks * 16;
            unsigned bh[4][2], bl[4][2];
#pragma unroll
            for (int nj = 0; nj < 4; nj++) {
                int boff = (wn * 32 + nj * 8 + g) * LDT + kk + 2 * t4;
                bh[nj][0] = *(const unsigned*)&sBh[boff];
                bh[nj][1] = *(const unsigned*)&sBh[boff + 8];
                bl[nj][0] = *(const unsigned*)&sBl[boff];
                bl[nj][1] = *(const unsigned*)&sBl[boff + 8];
            }
#pragma unroll
            for (int mi = 0; mi < MI; mi++) {
                int aoff = (wm * (MI * 16) + mi * 16 + g) * LDT + kk + 2 * t4;
                unsigned ah[4], al[4];
                ah[0] = *(const unsigned*)&sAh[aoff];
                ah[1] = *(const unsigned*)&sAh[aoff + 8 * LDT];
                ah[2] = *(const unsigned*)&sAh[aoff + 8];
                ah[3] = *(const unsigned*)&sAh[aoff + 8 * LDT + 8];
                al[0] = *(const unsigned*)&sAl[aoff];
                al[1] = *(const unsigned*)&sAl[aoff + 8 * LDT];
                al[2] = *(const unsigned*)&sAl[aoff + 8];
                al[3] = *(const unsigned*)&sAl[aoff + 8 * LDT + 8];
#pragma unroll
                for (int nj = 0; nj < 4; nj++) {
                    mma16816(c[mi][nj], ah, bh[nj]);
                    mma16816(c[mi][nj], ah, bl[nj]);
                    mma16816(c[mi][nj], al, bh[nj]);
                }
            }
        }
        __syncthreads();
    }

#pragma unroll
    for (int mi = 0; mi < MI; mi++) {
        int r = rowBase + wm * (MI * 16) + mi * 16 + g;
#pragma unroll
        for (int nj = 0; nj < 4; nj++) {
            int ccol = colBase + wn * 32 + nj * 8 + 2 * t4;
            *(float2*)&C[(size_t)r * Nc + ccol] = make_float2(c[mi][nj][0], c[mi][nj][1]);
            *(float2*)&C[(size_t)(r + 8) * Nc + ccol] = make_float2(c[mi][nj][2], c[mi][nj][3]);
        }
    }
}

// ---------------- SpMM gather: WPN warps per destination node ----------------
template<int D, int WPN, bool RELU, bool NSRC, bool WF32>
__global__ void k_spmm_gather(const float* __restrict__ Y,
                              const float* __restrict__ bias,
                              float* __restrict__ outF,
                              __nv_bfloat16* __restrict__ outHi,
                              __nv_bfloat16* __restrict__ outLo) {
    int gw = (blockIdx.x * blockDim.x + threadIdx.x) >> 5;
    int lane = threadIdx.x & 31;
    int node = gw / WPN, part = gw % WPN;
    if (node >= NN) return;
    const int off = part * (D / WPN) + lane * 4;
    const int beg = g_csr_off[node], end = g_csr_off[node + 1];
    const int* sp = g_csr_src;

    float4 a0 = {0,0,0,0}, a1 = {0,0,0,0}, a2 = {0,0,0,0}, a3 = {0,0,0,0};
    int e = beg;
#pragma unroll 1
    for (; e + 4 <= end; e += 4) {
        int s0 = __ldg(sp + e),     s1 = __ldg(sp + e + 1);
        int s2 = __ldg(sp + e + 2), s3 = __ldg(sp + e + 3);
        float4 u0 = __ldg((const float4*)(Y + (size_t)s0 * D + off));
        float4 u1 = __ldg((const float4*)(Y + (size_t)s1 * D + off));
        float4 u2 = __ldg((const float4*)(Y + (size_t)s2 * D + off));
        float4 u3 = __ldg((const float4*)(Y + (size_t)s3 * D + off));
        a0.x += u0.x; a0.y += u0.y; a0.z += u0.z; a0.w += u0.w;
        a1.x += u1.x; a1.y += u1.y; a1.z += u1.z; a1.w += u1.w;
        a2.x += u2.x; a2.y += u2.y; a2.z += u2.z; a2.w += u2.w;
        a3.x += u3.x; a3.y += u3.y; a3.z += u3.z; a3.w += u3.w;
    }
#pragma unroll 1
    for (; e < end; e++) {
        int s = __ldg(sp + e);
        float4 u = __ldg((const float4*)(Y + (size_t)s * D + off));
        a0.x += u.x; a0.y += u.y; a0.z += u.z; a0.w += u.w;
    }
    float v[4];
    v[0] = (a0.x + a1.x) + (a2.x + a3.x);
    v[1] = (a0.y + a1.y) + (a2.y + a3.y);
    v[2] = (a0.z + a1.z) + (a2.z + a3.z);
    v[3] = (a0.w + a1.w) + (a2.w + a3.w);

    const float nd = g_norm_dst[node];
    const float ns = NSRC ? g_norm_src[node] : 1.f;
    const size_t base = (size_t)node * D + off;

    __nv_bfloat162 h01, h23, l01, l23;
    float4 fout;
    float* fo = (float*)&fout;
#pragma unroll
    for (int j = 0; j < 4; j++) {
        float w = fmaf(v[j], nd, __ldg(&bias[off + j]));
        if (RELU) w = fmaxf(w, 0.f);
        fo[j] = w;
        w *= ns;
        __nv_bfloat16 h = __float2bfloat16(w);
        __nv_bfloat16 l = __float2bfloat16(w - __bfloat162float(h));
        if (j == 0) { h01.x = h; l01.x = l; }
        if (j == 1) { h01.y = h; l01.y = l; }
        if (j == 2) { h23.x = h; l23.x = l; }
        if (j == 3) { h23.y = h; l23.y = l; }
    }
    if (WF32) *(float4*)&outF[base] = fout;
    *(uint2*)&outHi[base] = make_uint2(*(unsigned*)&h01, *(unsigned*)&h23);
    *(uint2*)&outLo[base] = make_uint2(*(unsigned*)&l01, *(unsigned*)&l23);
}

// ================ reconstruction: logits = sigmoid(emb @ emb^T) ==============
// Triangular launch (2080 CTAs). Per k0 chunk: load hi+lo of A and B rows,
// all 3 split terms per round (4 rounds). Mirror via 64-row smem transpose.
__global__ __launch_bounds__(256, 2) void gemm_sym_sigmoid(float* __restrict__ L) {
    __shared__ __align__(16) char smem_raw[40960];
    __nv_bfloat16* sAh = (__nv_bfloat16*)smem_raw;
    __nv_bfloat16* sAl = sAh + 128 * LDT;
    __nv_bfloat16* sBh = sAl + 128 * LDT;
    __nv_bfloat16* sBl = sBh + 128 * LDT;
    float* tb = (float*)smem_raw;   // 64*132 floats = 33792B, reused after MMA

    const int t = blockIdx.x;
    int bi = (int)((129.0f - sqrtf(16641.0f - 8.0f * (float)t)) * 0.5f);
    while (bi * (129 - bi) / 2 > t) bi--;
    while ((bi + 1) * (128 - bi) / 2 <= t) bi++;
    const int bj = bi + (t - bi * (129 - bi) / 2);

    const int tid = threadIdx.x;
    const int warp = tid >> 5, lane = tid & 31;
    const int wm = warp & 1, wn = warp >> 1;
    const int g = lane >> 2, t4 = lane & 3;
    const int rowBase = bi * 128, colBase = bj * 128;

    float c[4][4][4];
#pragma unroll
    for (int mi = 0; mi < 4; mi++)
#pragma unroll
        for (int nj = 0; nj < 4; nj++)
#pragma unroll
            for (int q = 0; q < 4; q++) c[mi][nj][q] = 0.f;

#pragma unroll 1
    for (int k0 = 0; k0 < HD2; k0 += 32) {
#pragma unroll
        for (int i = tid; i < 128 * 8; i += 256) {
            int r = i >> 3, cc = i & 7;
            size_t ga = (size_t)(rowBase + r) * HD2 + k0 + cc * 4;
            size_t gb = (size_t)(colBase + r) * HD2 + k0 + cc * 4;
            *(uint2*)&sAh[r * LDT + cc * 4] = *(const uint2*)&g_ehi[ga];
            *(uint2*)&sAl[r * LDT + cc * 4] = *(const uint2*)&g_elo[ga];
            *(uint2*)&sBh[r * LDT + cc * 4] = *(const uint2*)&g_ehi[gb];
            *(uint2*)&sBl[r * LDT + cc * 4] = *(const uint2*)&g_elo[gb];
        }
        __syncthreads();
#pragma unroll
        for (int ks = 0; ks < 2; ks++) {
            const int kk = ks * 16;
            unsigned bh[4][2], bl[4][2];
#pragma unroll
            for (int nj = 0; nj < 4; nj++) {
                int boff = (wn * 32 + nj * 8 + g) * LDT + kk + 2 * t4;
                bh[nj][0] = *(const unsigned*)&sBh[boff];
                bh[nj][1] = *(const unsigned*)&sBh[boff + 8];
                bl[nj][0] = *(const unsigned*)&sBl[boff];
                bl[nj][1] = *(const unsigned*)&sBl[boff + 8];
            }
#pragma unroll
            for (int mi = 0; mi < 4; mi++) {
                int aoff = (wm * 64 + mi * 16 + g) * LDT + kk + 2 * t4;
                unsigned ah[4], al[4];
                ah[0] = *(const unsigned*)&sAh[aoff];
                ah[1] = *(const unsigned*)&sAh[aoff + 8 * LDT];
                ah[2] = *(const unsigned*)&sAh[aoff + 8];
                ah[3] = *(const unsigned*)&sAh[aoff + 8 * LDT + 8];
                al[0] = *(const unsigned*)&sAl[aoff];
                al[1] = *(const unsigned*)&sAl[aoff + 8 * LDT];
                al[2] = *(const unsigned*)&sAl[aoff + 8];
                al[3] = *(const unsigned*)&sAl[aoff + 8 * LDT + 8];
#pragma unroll
                for (int nj = 0; nj < 4; nj++) {
                    mma16816(c[mi][nj], ah, bh[nj]);
                    mma16816(c[mi][nj], ah, bl[nj]);
                    mma16816(c[mi][nj], al, bh[nj]);
                }
            }
        }
        __syncthreads();
    }

    // sigmoid
#pragma unroll
    for (int mi = 0; mi < 4; mi++)
#pragma unroll
        for (int nj = 0; nj < 4; nj++)
#pragma unroll
            for (int q = 0; q < 4; q++) c[mi][nj][q] = sigm(c[mi][nj][q]);

    // direct-orientation store
#pragma unroll
    for (int mi = 0; mi < 4; mi++) {
        int r = rowBase + wm * 64 + mi * 16 + g;
#pragma unroll
        for (int nj = 0; nj < 4; nj++) {
            int ccol = colBase + wn * 32 + nj * 8 + 2 * t4;
            *(float2*)&L[(size_t)r * NN + ccol] = make_float2(c[mi][nj][0], c[mi][nj][1]);
            *(float2*)&L[(size_t)(r + 8) * NN + ccol] = make_float2(c[mi][nj][2], c[mi][nj][3]);
        }
    }

    // mirrored store via 64-row smem transpose chunks
    if (bi != bj) {
#pragma unroll 1
        for (int ci = 0; ci < 2; ci++) {
            __syncthreads();
            if ((wn >> 1) == ci) {
#pragma unroll
                for (int mi = 0; mi < 4; mi++) {
                    int rr = wm * 64 + mi * 16 + g;
#pragma unroll
                    for (int nj = 0; nj < 4; nj++) {
                        int cc = (wn & 1) * 32 + nj * 8 + 2 * t4;
                        tb[cc * 132 + rr]           = c[mi][nj][0];
                        tb[(cc + 1) * 132 + rr]     = c[mi][nj][1];
                        tb[cc * 132 + rr + 8]       = c[mi][nj][2];
                        tb[(cc + 1) * 132 + rr + 8] = c[mi][nj][3];
                    }
                }
            }
            __syncthreads();
#pragma unroll 4
            for (int i = tid; i < 64 * 32; i += 256) {
                int r2 = i >> 5, c4 = i & 31;
                float4 v = *(float4*)&tb[r2 * 132 + c4 * 4];
                *(float4*)&L[(size_t)(colBase + ci * 64 + r2) * NN + rowBase + c4 * 4] = v;
            }
        }
    }
}

// ---------------- launch ------------------------------------------------------
extern "C" void kernel_launch(void* const* d_in, const int* in_sizes, int n_in,
                              void* d_out, int out_size) {
    const float* feat = (const float*)d_in[0];
    const int*   src  = (const int*)d_in[1];
    const int*   dst  = (const int*)d_in[2];
    const float* W1   = (const float*)d_in[3];
    const float* b1   = (const float*)d_in[4];
    const float* W2   = (const float*)d_in[5];
    const float* b2   = (const float*)d_in[6];

    float* out    = (float*)d_out;
    float* emb    = out;                       // [NN, HD2]
    float* logits = out + (size_t)NN * HD2;    // [NN, NN]

    float *y1, *y2;
    __nv_bfloat16 *fhi, *flo, *w1thi, *w1tlo, *w2thi, *w2tlo, *x1hi, *x1lo;
    cudaGetSymbolAddress((void**)&y1, g_y1);
    cudaGetSymbolAddress((void**)&y2, g_y2);
    cudaGetSymbolAddress((void**)&fhi, g_fhi);
    cudaGetSymbolAddress((void**)&flo, g_flo);
    cudaGetSymbolAddress((void**)&w1thi, g_w1thi);
    cudaGetSymbolAddress((void**)&w1tlo, g_w1tlo);
    cudaGetSymbolAddress((void**)&w2thi, g_w2thi);
    cudaGetSymbolAddress((void**)&w2tlo, g_w2tlo);
    cudaGetSymbolAddress((void**)&x1hi, g_x1hi);
    cudaGetSymbolAddress((void**)&x1lo, g_x1lo);
    __nv_bfloat16 *ehi, *elo;
    cudaGetSymbolAddress((void**)&ehi, g_ehi);
    cudaGetSymbolAddress((void**)&elo, g_elo);

    // host-side handles, created once (device work identical every call)
    static cudaStream_t st1 = nullptr, st2 = nullptr;
    static cudaEvent_t evR, evA, ev1, ev2;
    if (!st1) {
        cudaStreamCreateWithFlags(&st1, cudaStreamNonBlocking);
        cudaStreamCreateWithFlags(&st2, cudaStreamNonBlocking);
        cudaEventCreateWithFlags(&evR, cudaEventDisableTiming);
        cudaEventCreateWithFlags(&evA, cudaEventDisableTiming);
        cudaEventCreateWithFlags(&ev1, cudaEventDisableTiming);
        cudaEventCreateWithFlags(&ev2, cudaEventDisableTiming);
    }

    // fork: weight prep runs on st2, independent of everything
    cudaEventRecord(evR, 0);
    cudaStreamWaitEvent(st2, evR, 0);
    k_prep_w_both<<<(IND * HD1 + HD1 * HD2) / 256, 256, 0, st2>>>(W1, W2);
    cudaEventRecord(ev2, st2);

    // main: degrees -> norms -> feat prep
    k_zero_deg<<<NN / 256, 256>>>();
    k_degrees<<<EE / 256, 256>>>(src, dst);
    cudaEventRecord(evA, 0);

    // fork: CSR build on st1 (needs degrees only)
    cudaStreamWaitEvent(st1, evA, 0);
    k_scan_csr<<<1, 1024, 0, st1>>>();
    k_csr_fill<<<EE / 256, 256, 0, st1>>>(src, dst);
    cudaEventRecord(ev1, st1);

    k_norms<<<NN / 256, 256>>>();
    k_prep_feat<<<(NN * IND / 4) / 256, 256>>>(feat);

    // join weights before gemm1
    cudaStreamWaitEvent(0, ev2, 0);
    gemm_tc<4><<<dim3(HD1 / 128, NN / 128), 256>>>(fhi, flo, w1thi, w1tlo, y1, IND, HD1);

    // join CSR before spmm1
    cudaStreamWaitEvent(0, ev1, 0);
    k_spmm_gather<HD1, 2, true, true, false><<<(NN * 2 * 32) / 256, 256>>>(
        y1, b1, nullptr, x1hi, x1lo);

    gemm_tc<2><<<dim3(HD2 / 128, NN / 64), 256>>>(x1hi, x1lo, w2thi, w2tlo, y2, HD1, HD2);
    k_spmm_gather<HD2, 1, false, false, true><<<(NN * 32) / 256, 256>>>(
        y2, b2, emb, ehi, elo);

    // logits = sigmoid(emb @ emb^T), triangular symmetric tensor-core GEMM
    gemm_sym_sigmoid<<<2080, 256>>>(logits);
}

// round 6
// speedup vs baseline: 3.8652x; 1.0617x over previous
#include <cuda_runtime.h>
#include <cuda_bf16.h>
#include <math.h>

#define NN   8192
#define EE   262144
#define IND  512
#define HD1  256
#define HD2  128

// ---------------- scratch (device globals; no allocations allowed) ----------
__device__ int   g_deg_out[NN];
__device__ int   g_deg_in[NN];
__device__ float g_norm_src[NN];
__device__ float g_norm_dst[NN];
__device__ int   g_csr_off[NN + 1];
__device__ int   g_csr_pos[NN];
__device__ int   g_csr_src[EE];

__device__ __align__(128) __nv_bfloat16 g_fhi[(size_t)NN * IND];
__device__ __align__(128) __nv_bfloat16 g_flo[(size_t)NN * IND];
__device__ __align__(128) __nv_bfloat16 g_w1thi[(size_t)HD1 * IND];
__device__ __align__(128) __nv_bfloat16 g_w1tlo[(size_t)HD1 * IND];
__device__ __align__(128) __nv_bfloat16 g_w2thi[(size_t)HD2 * HD1];
__device__ __align__(128) __nv_bfloat16 g_w2tlo[(size_t)HD2 * HD1];
__device__ __align__(128) float g_y1[(size_t)NN * HD1];
__device__ __align__(128) float g_y2[(size_t)NN * HD2];
__device__ __align__(128) __nv_bfloat16 g_x1hi[(size_t)NN * HD1];
__device__ __align__(128) __nv_bfloat16 g_x1lo[(size_t)NN * HD1];
__device__ __align__(128) __nv_bfloat16 g_ehi[(size_t)NN * HD2];
__device__ __align__(128) __nv_bfloat16 g_elo[(size_t)NN * HD2];

// ---------------- cp.async helpers ------------------------------------------
__device__ __forceinline__ void cp16(void* smem, const void* g) {
    unsigned s = (unsigned)__cvta_generic_to_shared(smem);
    asm volatile("cp.async.cg.shared.global [%0], [%1], 16;" :: "r"(s), "l"(g));
}
__device__ __forceinline__ void cp_commit() {
    asm volatile("cp.async.commit_group;");
}
template<int N>
__device__ __forceinline__ void cp_wait() {
    asm volatile("cp.async.wait_group %0;" :: "n"(N));
}

// ---------------- graph preprocessing ---------------------------------------
__global__ void k_zero_deg() {
    int i = blockIdx.x * blockDim.x + threadIdx.x;
    if (i < NN) { g_deg_out[i] = 0; g_deg_in[i] = 0; }
}

__global__ void k_degrees(const int* __restrict__ src, const int* __restrict__ dst) {
    int e = blockIdx.x * blockDim.x + threadIdx.x;
    if (e < EE) {
        atomicAdd(&g_deg_out[src[e]], 1);
        atomicAdd(&g_deg_in[dst[e]], 1);
    }
}

__global__ void k_norms() {
    int i = blockIdx.x * blockDim.x + threadIdx.x;
    if (i < NN) {
        g_norm_src[i] = rsqrtf(fmaxf((float)g_deg_out[i], 1.f));
        g_norm_dst[i] = rsqrtf(fmaxf((float)g_deg_in[i], 1.f));
    }
}

// exclusive scan of in-degrees: 1024 threads, 8 items each, int4-coalesced
__global__ void k_scan_csr() {
    __shared__ int wsum[32];
    const int tid = threadIdx.x, lane = tid & 31, wid = tid >> 5;
    int4 d0 = *(const int4*)&g_deg_in[tid * 8];
    int4 d1 = *(const int4*)&g_deg_in[tid * 8 + 4];
    int v[8] = {d0.x, d0.y, d0.z, d0.w, d1.x, d1.y, d1.z, d1.w};
    int local[8];
    int s = 0;
#pragma unroll
    for (int j = 0; j < 8; j++) { local[j] = s; s += v[j]; }
    int inc = s;
#pragma unroll
    for (int d = 1; d < 32; d <<= 1) {
        int u = __shfl_up_sync(0xffffffffu, inc, d);
        if (lane >= d) inc += u;
    }
    if (lane == 31) wsum[wid] = inc;
    __syncthreads();
    if (wid == 0) {
        int w = wsum[lane];
        int i2 = w;
#pragma unroll
        for (int d = 1; d < 32; d <<= 1) {
            int u = __shfl_up_sync(0xffffffffu, i2, d);
            if (lane >= d) i2 += u;
        }
        wsum[lane] = i2 - w;   // exclusive
    }
    __syncthreads();
    int off = wsum[wid] + inc - s;
    int4 o0 = make_int4(off + local[0], off + local[1], off + local[2], off + local[3]);
    int4 o1 = make_int4(off + local[4], off + local[5], off + local[6], off + local[7]);
    *(int4*)&g_csr_off[tid * 8] = o0;
    *(int4*)&g_csr_off[tid * 8 + 4] = o1;
    *(int4*)&g_csr_pos[tid * 8] = o0;
    *(int4*)&g_csr_pos[tid * 8 + 4] = o1;
    if (tid == 0) g_csr_off[NN] = EE;
}

__global__ void k_csr_fill(const int* __restrict__ src, const int* __restrict__ dst) {
    int e = blockIdx.x * blockDim.x + threadIdx.x;
    if (e < EE) {
        int d = dst[e];
        int p = atomicAdd(&g_csr_pos[d], 1);
        g_csr_src[p] = src[e];
    }
}

// ---------------- prep: feature & weight bf16 splits ------------------------
__global__ void k_prep_feat(const float* __restrict__ feat) {
    int i4 = blockIdx.x * blockDim.x + threadIdx.x;
    if (i4 < (NN * IND) / 4) {
        int i = i4 * 4;
        int node = i >> 9;   // IND = 512
        float ns = g_norm_src[node];
        float4 u = __ldg((const float4*)&feat[i]);
        float x[4] = {u.x * ns, u.y * ns, u.z * ns, u.w * ns};
        __nv_bfloat162 h01, h23, l01, l23;
        __nv_bfloat16 h;
#define SPLIT1(v, HH, LL) h = __float2bfloat16(v); HH = h; LL = __float2bfloat16((v) - __bfloat162float(h));
        SPLIT1(x[0], h01.x, l01.x); SPLIT1(x[1], h01.y, l01.y);
        SPLIT1(x[2], h23.x, l23.x); SPLIT1(x[3], h23.y, l23.y);
        *(uint2*)&g_fhi[i] = make_uint2(*(unsigned*)&h01, *(unsigned*)&h23);
        *(uint2*)&g_flo[i] = make_uint2(*(unsigned*)&l01, *(unsigned*)&l23);
    }
}

// fused: W1 [IND][HD1] -> w1t hi/lo [HD1][IND];  W2 [HD1][HD2] -> w2t hi/lo
__global__ void k_prep_w_both(const float* __restrict__ W1, const float* __restrict__ W2) {
    int i = blockIdx.x * blockDim.x + threadIdx.x;
    if (i < IND * HD1) {
        int k = i / HD1, n = i % HD1;
        float x = W1[i];
        __nv_bfloat16 h = __float2bfloat16(x);
        g_w1thi[(size_t)n * IND + k] = h;
        g_w1tlo[(size_t)n * IND + k] = __float2bfloat16(x - __bfloat162float(h));
    } else {
        int j = i - IND * HD1;
        if (j < HD1 * HD2) {
            int k = j / HD2, n = j % HD2;
            float x = W2[j];
            __nv_bfloat16 h = __float2bfloat16(x);
            g_w2thi[(size_t)n * HD1 + k] = h;
            g_w2tlo[(size_t)n * HD1 + k] = __float2bfloat16(x - __bfloat162float(h));
        }
    }
}

// ---------------- bf16 split-precision MMA building blocks ------------------
__device__ __forceinline__ void mma16816(float* c, const unsigned* a, const unsigned* b) {
    asm volatile(
        "mma.sync.aligned.m16n8k16.row.col.f32.bf16.bf16.f32 "
        "{%0,%1,%2,%3}, {%4,%5,%6,%7}, {%8,%9}, {%0,%1,%2,%3};"
        : "+f"(c[0]), "+f"(c[1]), "+f"(c[2]), "+f"(c[3])
        : "r"(a[0]), "r"(a[1]), "r"(a[2]), "r"(a[3]), "r"(b[0]), "r"(b[1]));
}

__device__ __forceinline__ float sigm(float x) {
    return __fdividef(1.f, 1.f + __expf(-x));
}

#define LDT 40   // smem leading dim (halfwords) for 32-col bf16 tiles

// ---------------- layer GEMM: C[M,Nc] = (Ahi+Alo) @ (Bhi+Blo)^T --------------
// cp.async double-buffered; per chunk all 3 split terms. 8 warps (2x4).
template<int MI>
__global__ __launch_bounds__(256, 2) void gemm_tc(
    const __nv_bfloat16* __restrict__ Ahi, const __nv_bfloat16* __restrict__ Alo,
    const __nv_bfloat16* __restrict__ Bhi, const __nv_bfloat16* __restrict__ Blo,
    float* __restrict__ C, int K, int Nc) {
    constexpr int BM = MI * 32;
    constexpr int ASZ = BM * LDT * 2;        // bytes per A tile
    constexpr int BSZ = 128 * LDT * 2;
    constexpr int STG = 2 * ASZ + 2 * BSZ;   // bytes per stage
    extern __shared__ __align__(16) char dyn[];

    const int tid = threadIdx.x;
    const int warp = tid >> 5, lane = tid & 31;
    const int wm = warp & 1, wn = warp >> 1;
    const int g = lane >> 2, t4 = lane & 3;
    const int rowBase = blockIdx.y * BM, colBase = blockIdx.x * 128;

    float c[MI][4][4];
#pragma unroll
    for (int mi = 0; mi < MI; mi++)
#pragma unroll
        for (int nj = 0; nj < 4; nj++)
#pragma unroll
            for (int q = 0; q < 4; q++) c[mi][nj][q] = 0.f;

    const int R = K / 32;

    // stage loader
    auto load_stage = [&](int st, int k0) {
        char* base = dyn + st * STG;
        __nv_bfloat16* sAh = (__nv_bfloat16*)base;
        __nv_bfloat16* sAl = (__nv_bfloat16*)(base + ASZ);
        __nv_bfloat16* sBh = (__nv_bfloat16*)(base + 2 * ASZ);
        __nv_bfloat16* sBl = (__nv_bfloat16*)(base + 2 * ASZ + BSZ);
#pragma unroll
        for (int i = tid; i < BM * 4; i += 256) {
            int r = i >> 2, cc = i & 3;
            size_t gidx = (size_t)(rowBase + r) * K + k0 + cc * 8;
            int so = r * LDT + cc * 8;
            cp16(&sAh[so], &Ahi[gidx]);
            cp16(&sAl[so], &Alo[gidx]);
        }
#pragma unroll
        for (int i = tid; i < 128 * 4; i += 256) {
            int r = i >> 2, cc = i & 3;
            size_t gidx = (size_t)(colBase + r) * K + k0 + cc * 8;
            int so = r * LDT + cc * 8;
            cp16(&sBh[so], &Bhi[gidx]);
            cp16(&sBl[so], &Blo[gidx]);
        }
    };

    load_stage(0, 0);
    cp_commit();

#pragma unroll 1
    for (int rr = 0; rr < R; rr++) {
        if (rr + 1 < R) {
            load_stage((rr + 1) & 1, (rr + 1) * 32);
            cp_commit();
            cp_wait<1>();
        } else {
            cp_wait<0>();
        }
        __syncthreads();

        char* base = dyn + (rr & 1) * STG;
        const __nv_bfloat16* sAh = (const __nv_bfloat16*)base;
        const __nv_bfloat16* sAl = (const __nv_bfloat16*)(base + ASZ);
        const __nv_bfloat16* sBh = (const __nv_bfloat16*)(base + 2 * ASZ);
        const __nv_bfloat16* sBl = (const __nv_bfloat16*)(base + 2 * ASZ + BSZ);

#pragma unroll
        for (int ks = 0; ks < 2; ks++) {
            const int kk = ks * 16;
            unsigned bh[4][2], bl[4][2];
#pragma unroll
            for (int nj = 0; nj < 4; nj++) {
                int boff = (wn * 32 + nj * 8 + g) * LDT + kk + 2 * t4;
                bh[nj][0] = *(const unsigned*)&sBh[boff];
                bh[nj][1] = *(const unsigned*)&sBh[boff + 8];
                bl[nj][0] = *(const unsigned*)&sBl[boff];
                bl[nj][1] = *(const unsigned*)&sBl[boff + 8];
            }
#pragma unroll
            for (int mi = 0; mi < MI; mi++) {
                int aoff = (wm * (MI * 16) + mi * 16 + g) * LDT + kk + 2 * t4;
                unsigned ah[4], al[4];
                ah[0] = *(const unsigned*)&sAh[aoff];
                ah[1] = *(const unsigned*)&sAh[aoff + 8 * LDT];
                ah[2] = *(const unsigned*)&sAh[aoff + 8];
                ah[3] = *(const unsigned*)&sAh[aoff + 8 * LDT + 8];
                al[0] = *(const unsigned*)&sAl[aoff];
                al[1] = *(const unsigned*)&sAl[aoff + 8 * LDT];
                al[2] = *(const unsigned*)&sAl[aoff + 8];
                al[3] = *(const unsigned*)&sAl[aoff + 8 * LDT + 8];
#pragma unroll
                for (int nj = 0; nj < 4; nj++) {
                    mma16816(c[mi][nj], ah, bh[nj]);
                    mma16816(c[mi][nj], ah, bl[nj]);
                    mma16816(c[mi][nj], al, bh[nj]);
                }
            }
        }
        __syncthreads();
    }

#pragma unroll
    for (int mi = 0; mi < MI; mi++) {
        int r = rowBase + wm * (MI * 16) + mi * 16 + g;
#pragma unroll
        for (int nj = 0; nj < 4; nj++) {
            int ccol = colBase + wn * 32 + nj * 8 + 2 * t4;
            *(float2*)&C[(size_t)r * Nc + ccol] = make_float2(c[mi][nj][0], c[mi][nj][1]);
            *(float2*)&C[(size_t)(r + 8) * Nc + ccol] = make_float2(c[mi][nj][2], c[mi][nj][3]);
        }
    }
}

// ---------------- SpMM gather: WPN warps per destination node ----------------
template<int D, int WPN, bool RELU, bool NSRC, bool WF32>
__global__ void k_spmm_gather(const float* __restrict__ Y,
                              const float* __restrict__ bias,
                              float* __restrict__ outF,
                              __nv_bfloat16* __restrict__ outHi,
                              __nv_bfloat16* __restrict__ outLo) {
    int gw = (blockIdx.x * blockDim.x + threadIdx.x) >> 5;
    int lane = threadIdx.x & 31;
    int node = gw / WPN, part = gw % WPN;
    if (node >= NN) return;
    const int off = part * (D / WPN) + lane * 4;
    const int beg = g_csr_off[node], end = g_csr_off[node + 1];
    const int* sp = g_csr_src;

    float4 acc[8];
#pragma unroll
    for (int j = 0; j < 8; j++) acc[j] = make_float4(0.f, 0.f, 0.f, 0.f);

    int e = beg;
#pragma unroll 1
    for (; e + 8 <= end; e += 8) {
        int sdx[8];
#pragma unroll
        for (int j = 0; j < 8; j++) sdx[j] = __ldg(sp + e + j);
#pragma unroll
        for (int j = 0; j < 8; j++) {
            float4 u = __ldg((const float4*)(Y + (size_t)sdx[j] * D + off));
            acc[j].x += u.x; acc[j].y += u.y; acc[j].z += u.z; acc[j].w += u.w;
        }
    }
#pragma unroll 1
    for (; e < end; e++) {
        int s = __ldg(sp + e);
        float4 u = __ldg((const float4*)(Y + (size_t)s * D + off));
        acc[0].x += u.x; acc[0].y += u.y; acc[0].z += u.z; acc[0].w += u.w;
    }
    float v[4];
    v[0] = ((acc[0].x + acc[1].x) + (acc[2].x + acc[3].x)) + ((acc[4].x + acc[5].x) + (acc[6].x + acc[7].x));
    v[1] = ((acc[0].y + acc[1].y) + (acc[2].y + acc[3].y)) + ((acc[4].y + acc[5].y) + (acc[6].y + acc[7].y));
    v[2] = ((acc[0].z + acc[1].z) + (acc[2].z + acc[3].z)) + ((acc[4].z + acc[5].z) + (acc[6].z + acc[7].z));
    v[3] = ((acc[0].w + acc[1].w) + (acc[2].w + acc[3].w)) + ((acc[4].w + acc[5].w) + (acc[6].w + acc[7].w));

    const float nd = g_norm_dst[node];
    const float ns = NSRC ? g_norm_src[node] : 1.f;
    const size_t base = (size_t)node * D + off;

    __nv_bfloat162 h01, h23, l01, l23;
    float4 fout;
    float* fo = (float*)&fout;
#pragma unroll
    for (int j = 0; j < 4; j++) {
        float w = fmaf(v[j], nd, __ldg(&bias[off + j]));
        if (RELU) w = fmaxf(w, 0.f);
        fo[j] = w;
        w *= ns;
        __nv_bfloat16 h = __float2bfloat16(w);
        __nv_bfloat16 l = __float2bfloat16(w - __bfloat162float(h));
        if (j == 0) { h01.x = h; l01.x = l; }
        if (j == 1) { h01.y = h; l01.y = l; }
        if (j == 2) { h23.x = h; l23.x = l; }
        if (j == 3) { h23.y = h; l23.y = l; }
    }
    if (WF32) *(float4*)&outF[base] = fout;
    *(uint2*)&outHi[base] = make_uint2(*(unsigned*)&h01, *(unsigned*)&h23);
    *(uint2*)&outLo[base] = make_uint2(*(unsigned*)&l01, *(unsigned*)&l23);
}

// ================ reconstruction: logits = sigmoid(emb @ emb^T) ==============
// Triangular launch (2080 CTAs). cp.async double-buffered (4 rounds of K=32).
// Mirror via 64-row smem transpose reusing the pipeline buffers.
__global__ __launch_bounds__(256, 2) void gemm_sym_sigmoid(float* __restrict__ L) {
    constexpr int TSZ = 128 * LDT * 2;     // bytes per tile
    constexpr int STG = 4 * TSZ;           // bytes per stage (Ah, Al, Bh, Bl)
    extern __shared__ __align__(16) char dyn[];
    float* tb = (float*)dyn;               // 64*132 floats, reused after MMA

    const int t = blockIdx.x;
    int bi = (int)((129.0f - sqrtf(16641.0f - 8.0f * (float)t)) * 0.5f);
    while (bi * (129 - bi) / 2 > t) bi--;
    while ((bi + 1) * (128 - bi) / 2 <= t) bi++;
    const int bj = bi + (t - bi * (129 - bi) / 2);

    const int tid = threadIdx.x;
    const int warp = tid >> 5, lane = tid & 31;
    const int wm = warp & 1, wn = warp >> 1;
    const int g = lane >> 2, t4 = lane & 3;
    const int rowBase = bi * 128, colBase = bj * 128;

    float c[4][4][4];
#pragma unroll
    for (int mi = 0; mi < 4; mi++)
#pragma unroll
        for (int nj = 0; nj < 4; nj++)
#pragma unroll
            for (int q = 0; q < 4; q++) c[mi][nj][q] = 0.f;

    auto load_stage = [&](int st, int k0) {
        char* base = dyn + st * STG;
        __nv_bfloat16* sAh = (__nv_bfloat16*)base;
        __nv_bfloat16* sAl = (__nv_bfloat16*)(base + TSZ);
        __nv_bfloat16* sBh = (__nv_bfloat16*)(base + 2 * TSZ);
        __nv_bfloat16* sBl = (__nv_bfloat16*)(base + 3 * TSZ);
#pragma unroll
        for (int i = tid; i < 128 * 4; i += 256) {
            int r = i >> 2, cc = i & 3;
            size_t ga = (size_t)(rowBase + r) * HD2 + k0 + cc * 8;
            size_t gb = (size_t)(colBase + r) * HD2 + k0 + cc * 8;
            int so = r * LDT + cc * 8;
            cp16(&sAh[so], &g_ehi[ga]);
            cp16(&sAl[so], &g_elo[ga]);
            cp16(&sBh[so], &g_ehi[gb]);
            cp16(&sBl[so], &g_elo[gb]);
        }
    };

    load_stage(0, 0);
    cp_commit();

#pragma unroll 1
    for (int rr = 0; rr < 4; rr++) {
        if (rr < 3) {
            load_stage((rr + 1) & 1, (rr + 1) * 32);
            cp_commit();
            cp_wait<1>();
        } else {
            cp_wait<0>();
        }
        __syncthreads();

        char* base = dyn + (rr & 1) * STG;
        const __nv_bfloat16* sAh = (const __nv_bfloat16*)base;
        const __nv_bfloat16* sAl = (const __nv_bfloat16*)(base + TSZ);
        const __nv_bfloat16* sBh = (const __nv_bfloat16*)(base + 2 * TSZ);
        const __nv_bfloat16* sBl = (const __nv_bfloat16*)(base + 3 * TSZ);

#pragma unroll
        for (int ks = 0; ks < 2; ks++) {
            const int kk = ks * 16;
            unsigned bh[4][2], bl[4][2];
#pragma unroll
            for (int nj = 0; nj < 4; nj++) {
                int boff = (wn * 32 + nj * 8 + g) * LDT + kk + 2 * t4;
                bh[nj][0] = *(const unsigned*)&sBh[boff];
                bh[nj][1] = *(const unsigned*)&sBh[boff + 8];
                bl[nj][0] = *(const unsigned*)&sBl[boff];
                bl[nj][1] = *(const unsigned*)&sBl[boff + 8];
            }
#pragma unroll
            for (int mi = 0; mi < 4; mi++) {
                int aoff = (wm * 64 + mi * 16 + g) * LDT + kk + 2 * t4;
                unsigned ah[4], al[4];
                ah[0] = *(const unsigned*)&sAh[aoff];
                ah[1] = *(const unsigned*)&sAh[aoff + 8 * LDT];
                ah[2] = *(const unsigned*)&sAh[aoff + 8];
                ah[3] = *(const unsigned*)&sAh[aoff + 8 * LDT + 8];
                al[0] = *(const unsigned*)&sAl[aoff];
                al[1] = *(const unsigned*)&sAl[aoff + 8 * LDT];
                al[2] = *(const unsigned*)&sAl[aoff + 8];
                al[3] = *(const unsigned*)&sAl[aoff + 8 * LDT + 8];
#pragma unroll
                for (int nj = 0; nj < 4; nj++) {
                    mma16816(c[mi][nj], ah, bh[nj]);
                    mma16816(c[mi][nj], ah, bl[nj]);
                    mma16816(c[mi][nj], al, bh[nj]);
                }
            }
        }
        __syncthreads();
    }

    // sigmoid
#pragma unroll
    for (int mi = 0; mi < 4; mi++)
#pragma unroll
        for (int nj = 0; nj < 4; nj++)
#pragma unroll
            for (int q = 0; q < 4; q++) c[mi][nj][q] = sigm(c[mi][nj][q]);

    // direct-orientation store
#pragma unroll
    for (int mi = 0; mi < 4; mi++) {
        int r = rowBase + wm * 64 + mi * 16 + g;
#pragma unroll
        for (int nj = 0; nj < 4; nj++) {
            int ccol = colBase + wn * 32 + nj * 8 + 2 * t4;
            *(float2*)&L[(size_t)r * NN + ccol] = make_float2(c[mi][nj][0], c[mi][nj][1]);
            *(float2*)&L[(size_t)(r + 8) * NN + ccol] = make_float2(c[mi][nj][2], c[mi][nj][3]);
        }
    }

    // mirrored store via 64-row smem transpose chunks
    if (bi != bj) {
#pragma unroll 1
        for (int ci = 0; ci < 2; ci++) {
            __syncthreads();
            if ((wn >> 1) == ci) {
#pragma unroll
                for (int mi = 0; mi < 4; mi++) {
                    int rr = wm * 64 + mi * 16 + g;
#pragma unroll
                    for (int nj = 0; nj < 4; nj++) {
                        int cc = (wn & 1) * 32 + nj * 8 + 2 * t4;
                        tb[cc * 132 + rr]           = c[mi][nj][0];
                        tb[(cc + 1) * 132 + rr]     = c[mi][nj][1];
                        tb[cc * 132 + rr + 8]       = c[mi][nj][2];
                        tb[(cc + 1) * 132 + rr + 8] = c[mi][nj][3];
                    }
                }
            }
            __syncthreads();
#pragma unroll 4
            for (int i = tid; i < 64 * 32; i += 256) {
                int r2 = i >> 5, c4 = i & 31;
                float4 v = *(float4*)&tb[r2 * 132 + c4 * 4];
                *(float4*)&L[(size_t)(colBase + ci * 64 + r2) * NN + rowBase + c4 * 4] = v;
            }
        }
    }
}

// ---------------- launch ------------------------------------------------------
extern "C" void kernel_launch(void* const* d_in, const int* in_sizes, int n_in,
                              void* d_out, int out_size) {
    const float* feat = (const float*)d_in[0];
    const int*   src  = (const int*)d_in[1];
    const int*   dst  = (const int*)d_in[2];
    const float* W1   = (const float*)d_in[3];
    const float* b1   = (const float*)d_in[4];
    const float* W2   = (const float*)d_in[5];
    const float* b2   = (const float*)d_in[6];

    float* out    = (float*)d_out;
    float* emb    = out;                       // [NN, HD2]
    float* logits = out + (size_t)NN * HD2;    // [NN, NN]

    float *y1, *y2;
    __nv_bfloat16 *fhi, *flo, *w1thi, *w1tlo, *w2thi, *w2tlo, *x1hi, *x1lo, *ehi, *elo;
    cudaGetSymbolAddress((void**)&y1, g_y1);
    cudaGetSymbolAddress((void**)&y2, g_y2);
    cudaGetSymbolAddress((void**)&fhi, g_fhi);
    cudaGetSymbolAddress((void**)&flo, g_flo);
    cudaGetSymbolAddress((void**)&w1thi, g_w1thi);
    cudaGetSymbolAddress((void**)&w1tlo, g_w1tlo);
    cudaGetSymbolAddress((void**)&w2thi, g_w2thi);
    cudaGetSymbolAddress((void**)&w2tlo, g_w2tlo);
    cudaGetSymbolAddress((void**)&x1hi, g_x1hi);
    cudaGetSymbolAddress((void**)&x1lo, g_x1lo);
    cudaGetSymbolAddress((void**)&ehi, g_ehi);
    cudaGetSymbolAddress((void**)&elo, g_elo);

    constexpr int SMEM_G1 = 2 * (2 * 128 * LDT * 2 + 2 * 128 * LDT * 2);   // 81920
    constexpr int SMEM_G2 = 2 * (2 * 64 * LDT * 2 + 2 * 128 * LDT * 2);    // 61440
    constexpr int SMEM_RC = 2 * (4 * 128 * LDT * 2);                       // 81920

    // host-side handles, created once (device work identical every call)
    static cudaStream_t st1 = nullptr, st2 = nullptr;
    static cudaEvent_t evR, evA, ev1, ev2;
    if (!st1) {
        cudaStreamCreateWithFlags(&st1, cudaStreamNonBlocking);
        cudaStreamCreateWithFlags(&st2, cudaStreamNonBlocking);
        cudaEventCreateWithFlags(&evR, cudaEventDisableTiming);
        cudaEventCreateWithFlags(&evA, cudaEventDisableTiming);
        cudaEventCreateWithFlags(&ev1, cudaEventDisableTiming);
        cudaEventCreateWithFlags(&ev2, cudaEventDisableTiming);
        cudaFuncSetAttribute(gemm_tc<4>, cudaFuncAttributeMaxDynamicSharedMemorySize, SMEM_G1);
        cudaFuncSetAttribute(gemm_tc<2>, cudaFuncAttributeMaxDynamicSharedMemorySize, SMEM_G2);
        cudaFuncSetAttribute(gemm_sym_sigmoid, cudaFuncAttributeMaxDynamicSharedMemorySize, SMEM_RC);
    }

    // fork: weight prep runs on st2, independent of everything
    cudaEventRecord(evR, 0);
    cudaStreamWaitEvent(st2, evR, 0);
    k_prep_w_both<<<(IND * HD1 + HD1 * HD2) / 256, 256, 0, st2>>>(W1, W2);
    cudaEventRecord(ev2, st2);

    // main: degrees -> norms -> feat prep
    k_zero_deg<<<NN / 256, 256>>>();
    k_degrees<<<EE / 256, 256>>>(src, dst);
    cudaEventRecord(evA, 0);

    // fork: CSR build on st1 (needs degrees only)
    cudaStreamWaitEvent(st1, evA, 0);
    k_scan_csr<<<1, 1024, 0, st1>>>();
    k_csr_fill<<<EE / 256, 256, 0, st1>>>(src, dst);
    cudaEventRecord(ev1, st1);

    k_norms<<<NN / 256, 256>>>();
    k_prep_feat<<<(NN * IND / 4) / 256, 256>>>(feat);

    // join weights before gemm1
    cudaStreamWaitEvent(0, ev2, 0);
    gemm_tc<4><<<dim3(HD1 / 128, NN / 128), 256, SMEM_G1>>>(fhi, flo, w1thi, w1tlo, y1, IND, HD1);

    // join CSR before spmm1
    cudaStreamWaitEvent(0, ev1, 0);
    k_spmm_gather<HD1, 2, true, true, false><<<(NN * 2 * 32) / 256, 256>>>(
        y1, b1, nullptr, x1hi, x1lo);

    gemm_tc<2><<<dim3(HD2 / 128, NN / 64), 256, SMEM_G2>>>(x1hi, x1lo, w2thi, w2tlo, y2, HD1, HD2);
    k_spmm_gather<HD2, 1, false, false, true><<<(NN * 32) / 256, 256>>>(
        y2, b2, emb, ehi, elo);

    // logits = sigmoid(emb @ emb^T), triangular symmetric tensor-core GEMM
    gemm_sym_sigmoid<<<2080, 256, SMEM_RC>>>(logits);
}